// round 10
// baseline (speedup 1.0000x reference)
#include <cuda_runtime.h>
#include <math.h>
#include <math_constants.h>
#include <stdint.h>

#define BB 2
#define TT 2048
#define SS 2048
#define DD 256
#define HH 8
#define FFD 2048
#define VOC 25426
#define VOCP 25472              // padded vocab (199*128)
#define BT (BB*TT)
#define QH (BB*HH*TT)
#define NSPLIT 8

// ---------------- scratch ----------------
#define SLAB 1048576
#define O_X0   (0*SLAB)
#define O_X1   (1*SLAB)
#define O_X2   (2*SLAB)
#define O_X3   (3*SLAB)
#define O_Q    (4*SLAB)
#define O_K    (5*SLAB)
#define O_V    (6*SLAB)
#define O_ATT  (7*SLAB)
#define O_PROJ (8*SLAB)
#define O_ENCZ (9*SLAB)
#define O_FF   ((size_t)10*SLAB)                 // 8 slabs
#define O_PO   ((size_t)18*SLAB)                 // NSPLIT*QH*32 = 8 slabs
#define O_PM   ((size_t)26*SLAB)
#define O_PL   ((size_t)26*SLAB + NSPLIT*QH)
#define O_WATT ((size_t)27*SLAB)                 // 8 x 65536
#define O_W1   (O_WATT + 8*65536)
#define O_W2   (O_W1 + 524288)
#define O_WF   (O_W2 + 524288)                   // 256*25472
#define SCRATCH_FLOATS ((size_t)35*SLAB)

__device__ float g_scratch[SCRATCH_FLOATS];
__device__ float g_padbuf[BT];

__device__ __forceinline__ uint32_t f2tf(float f) {
    uint32_t u; asm("cvt.rna.tf32.f32 %0, %1;" : "=r"(u) : "f"(f)); return u;
}
__device__ __forceinline__ float tfr(float f) { return __uint_as_float(f2tf(f)); }
__device__ __forceinline__ float gelu_f(float v) {
    return 0.5f*v*(1.0f + erff(v*0.70710678118654752f));
}
__device__ __forceinline__ void cp16(uint32_t dst, const void* src) {
    asm volatile("cp.async.cg.shared.global [%0], [%1], 16;" :: "r"(dst), "l"(src));
}

// ---------------- weight pre-conversion (RNA tf32) ----------------
__global__ void k_conv(const float* __restrict__ src, float* __restrict__ dst, int n)
{
    int i = blockIdx.x*256 + threadIdx.x;
    if (i < n) dst[i] = tfr(src[i]);
}
__global__ void k_prep8(const float* w0, const float* w1, const float* w2, const float* w3,
                        const float* w4, const float* w5, const float* w6, const float* w7)
{
    int idx = blockIdx.x*256 + threadIdx.x;
    int w = idx >> 16, r = idx & 65535;
    const float* src;
    switch (w) {
        case 0: src = w0; break; case 1: src = w1; break;
        case 2: src = w2; break; case 3: src = w3; break;
        case 4: src = w4; break; case 5: src = w5; break;
        case 6: src = w6; break; default: src = w7; break;
    }
    g_scratch[O_WATT + (size_t)w*65536 + r] = tfr(src[r]);
}
__global__ void k_convpad(const float* __restrict__ src)   // Wf -> padded, no div/mod
{
    int k = blockIdx.y;
    int n = blockIdx.x*128 + threadIdx.x;
    float v = (n < VOC) ? tfr(src[(size_t)k*VOC + n]) : 0.0f;
    g_scratch[O_WF + (size_t)k*VOCP + n] = v;
}

// ---------------- embedding + positional encoding ----------------
__global__ void k_embed(const int* __restrict__ tgt_in,
                        const float* __restrict__ emb,
                        float* __restrict__ out_ids, int write_ids)
{
    int r = blockIdx.x;
    int d = threadIdx.x;
    int b = r / TT, t = r % TT;
    int id = (t == 0) ? VOC : tgt_in[b*(TT-1) + (t-1)];
    if (d == 0) {
        g_padbuf[r] = (id != 0) ? 1.0f : 0.0f;
        if (write_ids) out_ids[r] = (t == 0) ? 0.0f : (float)id;
    }
    int i2 = d & ~1;
    float div = __expf(-(float)i2 * (9.210340371976184f / 256.0f));
    float ang = (float)t * div;
    float pe  = (d & 1) ? cosf(ang) : sinf(ang);
    g_scratch[O_X0 + (size_t)r*DD + d] = tfr(2.0f*emb[(size_t)id*DD + d] + pe);
}

__global__ void k_encz(const int* __restrict__ src, const float* __restrict__ enc)
{
    int r = blockIdx.x;
    int d = threadIdx.x;
    g_scratch[O_ENCZ + (size_t)r*DD + d] = (src[r] != 0) ? tfr(enc[(size_t)r*DD + d]) : 0.0f;
}

// ================= 128x128 pipelined TF32 GEMM (small GEMMs) ==============
#define SMEM_GEMM_BYTES ((2*128*32 + 2*32*136)*4)

__device__ __forceinline__ void gemm128(
    const float* __restrict__ A, const float* __restrict__ Bm,
    const float* __restrict__ bias, float* __restrict__ C,
    int M, int N, int K, int ldb, int act, int roundOut, uint32_t* sh)
{
    uint32_t* BsW = sh + 8192;
    uint32_t shA = (uint32_t)__cvta_generic_to_shared(sh);
    uint32_t shB = (uint32_t)__cvta_generic_to_shared(sh + 8192);

    int tid = threadIdx.x;
    int lane = tid & 31, warp = tid >> 5;
    int wm0 = (warp >> 2) * 64, wn0 = (warp & 3) * 32;
    int m0 = blockIdx.y * 128, n0 = blockIdx.x * 128;

    int ar  = tid >> 3, ac16 = tid & 7;
    const float* srcA0 = A + (size_t)(m0 + ar)*K + ac16*4;
    uint32_t dstA0 = shA + (uint32_t)((ar*32 + ((ac16 ^ (ar & 7)) << 2)) << 2);
    int br  = tid >> 5, bc = tid & 31;
    const float* srcB0 = Bm + (size_t)br*ldb + n0 + bc*4;
    uint32_t dstB0 = shB + (uint32_t)((br*136 + bc*4) << 2);

    int arow  = (lane & 7) | (lane & 8);
    int khalf = lane >> 4;
    int sw    = lane & 7;
    uint32_t baseA = shA + (uint32_t)(((wm0 + arow)*32) << 2);
    int baseB = (lane & 3)*136 + wn0 + (lane >> 2);

    float acc[4][4][4];
    #pragma unroll
    for (int i = 0; i < 4; i++)
        #pragma unroll
        for (int j = 0; j < 4; j++) {
            acc[i][j][0]=0.f; acc[i][j][1]=0.f; acc[i][j][2]=0.f; acc[i][j][3]=0.f;
        }

    int nk = K >> 5;
    #pragma unroll
    for (int i = 0; i < 4; i++) cp16(dstA0 + i*4096u, srcA0 + (size_t)i*32*K);
    #pragma unroll
    for (int i = 0; i < 4; i++) cp16(dstB0 + i*4352u, srcB0 + (size_t)i*8*ldb);
    asm volatile("cp.async.commit_group;");
    asm volatile("cp.async.wait_group 0;");
    __syncthreads();

    for (int kt = 0; kt < nk; kt++) {
        int cur = kt & 1;
        if (kt + 1 < nk) {
            int k0 = (kt + 1) << 5;
            uint32_t abuf = dstA0 + (cur ^ 1)*16384u;
            const float* asrc = srcA0 + k0;
            #pragma unroll
            for (int i = 0; i < 4; i++) cp16(abuf + i*4096u, asrc + (size_t)i*32*K);
            uint32_t bbuf = dstB0 + (cur ^ 1)*17408u;
            const float* bsrc = srcB0 + (size_t)k0*ldb;
            #pragma unroll
            for (int i = 0; i < 4; i++) cp16(bbuf + i*4352u, bsrc + (size_t)i*8*ldb);
            asm volatile("cp.async.commit_group;");
        }

        uint32_t aB = baseA + cur*16384u;
        const uint32_t* bW = BsW + cur*4352 + baseB;

        #pragma unroll
        for (int ks = 0; ks < 4; ks++) {
            uint32_t af[4][4], bfr[4][2];
            uint32_t csw = (uint32_t)((((ks*2 + khalf) ^ sw) << 4));
            #pragma unroll
            for (int mt = 0; mt < 4; mt++) {
                uint32_t addr = aB + mt*2048u + csw;
                asm volatile(
                    "ldmatrix.sync.aligned.m8n8.x4.shared.b16 {%0,%1,%2,%3}, [%4];"
                    : "=r"(af[mt][0]), "=r"(af[mt][1]), "=r"(af[mt][2]), "=r"(af[mt][3])
                    : "r"(addr));
            }
            #pragma unroll
            for (int nt = 0; nt < 4; nt++) {
                bfr[nt][0] = bW[ks*1088 + nt*8];
                bfr[nt][1] = bW[ks*1088 + 544 + nt*8];
            }
            #pragma unroll
            for (int mt = 0; mt < 4; mt++)
                #pragma unroll
                for (int nt = 0; nt < 4; nt++)
                    asm volatile(
                        "mma.sync.aligned.m16n8k8.row.col.f32.tf32.tf32.f32 "
                        "{%0,%1,%2,%3}, {%4,%5,%6,%7}, {%8,%9}, {%0,%1,%2,%3};"
                        : "+f"(acc[mt][nt][0]), "+f"(acc[mt][nt][1]),
                          "+f"(acc[mt][nt][2]), "+f"(acc[mt][nt][3])
                        : "r"(af[mt][0]), "r"(af[mt][1]),
                          "r"(af[mt][2]), "r"(af[mt][3]),
                          "r"(bfr[nt][0]), "r"(bfr[nt][1]));
        }

        if (kt + 1 < nk) {
            asm volatile("cp.async.wait_group 0;");
            __syncthreads();
        }
    }

    #pragma unroll
    for (int mt = 0; mt < 4; mt++) {
        int row0 = m0 + wm0 + mt*16 + (lane >> 2);
        #pragma unroll
        for (int nt = 0; nt < 4; nt++) {
            int col = n0 + wn0 + nt*8 + 2*(lane & 3);
            #pragma unroll
            for (int h = 0; h < 2; h++) {
                int rw = row0 + h*8;
                float v0 = acc[mt][nt][h*2+0];
                float v1 = acc[mt][nt][h*2+1];
                if (col + 1 < N) {
                    if (bias) { v0 += bias[col]; v1 += bias[col+1]; }
                    if (act)  { v0 = gelu_f(v0); v1 = gelu_f(v1); }
                    if (roundOut) { v0 = tfr(v0); v1 = tfr(v1); }
                    float2 o; o.x = v0; o.y = v1;
                    *(float2*)&C[(size_t)rw*N + col] = o;
                } else if (col < N) {
                    if (bias) v0 += bias[col];
                    if (act)  v0 = gelu_f(v0);
                    if (roundOut) v0 = tfr(v0);
                    C[(size_t)rw*N + col] = v0;
                }
            }
        }
    }
}

__global__ void __launch_bounds__(256)
k_mma(const float* __restrict__ A, const float* __restrict__ Bm,
      const float* __restrict__ bias, float* __restrict__ C,
      int M, int N, int K, int ldb, int act, int roundOut)
{
    extern __shared__ uint32_t sh[];
    gemm128(A, Bm, bias, C, M, N, K, ldb, act, roundOut, sh);
}

__global__ void __launch_bounds__(256)
k_mma3(const float* a0, const float* a1, const float* a2,
       const float* w0, const float* w1, const float* w2,
       float* c0, float* c1, float* c2, int M)
{
    extern __shared__ uint32_t sh[];
    const float* A; const float* W; float* C;
    if (blockIdx.z == 0)      { A = a0; W = w0; C = c0; }
    else if (blockIdx.z == 1) { A = a1; W = w1; C = c1; }
    else                      { A = a2; W = w2; C = c2; }
    gemm128(A, W, nullptr, C, M, DD, DD, DD, 0, 0, sh);
}

// ================= 256x128 TF32 GEMM (big GEMMs, higher intensity) ========
// 8 warps as 4(m) x 2(n), warp tile 64x64. smem: A 2x(256x32) SW128,
// B 2x(32x136). 100352 bytes. Supports K-split via blockIdx.z.
#define SMEM_G256 ((2*256*32 + 2*32*136)*4)

__global__ void __launch_bounds__(256, 1)
k_mma256(const float* __restrict__ A, const float* __restrict__ Bm,
         const float* __restrict__ bias, float* __restrict__ Cbase,
         int M, int N, int lda, int ldb, int kLen, int zStrideC,
         int act, int roundOut)
{
    extern __shared__ uint32_t sh[];
    uint32_t* BsW = sh + 16384;
    uint32_t shA = (uint32_t)__cvta_generic_to_shared(sh);
    uint32_t shB = (uint32_t)__cvta_generic_to_shared(sh + 16384);

    int tid = threadIdx.x;
    int lane = tid & 31, warp = tid >> 5;
    int wm0 = (warp & 3) * 64, wn0 = (warp >> 2) * 64;
    int m0 = blockIdx.y * 256, n0 = blockIdx.x * 128;
    int kStart = blockIdx.z * kLen;
    float* C = Cbase + (size_t)blockIdx.z * zStrideC;

    int ar  = tid >> 3, ac16 = tid & 7;
    const float* srcA0 = A + (size_t)(m0 + ar)*lda + kStart + ac16*4;
    uint32_t dstA0 = shA + (uint32_t)((ar*32 + ((ac16 ^ (ar & 7)) << 2)) << 2);
    int br  = tid >> 5, bc = tid & 31;
    const float* srcB0 = Bm + (size_t)(kStart + br)*ldb + n0 + bc*4;
    uint32_t dstB0 = shB + (uint32_t)((br*136 + bc*4) << 2);

    int arow  = (lane & 7) | (lane & 8);
    int khalf = lane >> 4;
    int sw    = lane & 7;
    uint32_t baseA = shA + (uint32_t)(((wm0 + arow)*32) << 2);
    int baseB = (lane & 3)*136 + wn0 + (lane >> 2);

    float acc[4][8][4];
    #pragma unroll
    for (int i = 0; i < 4; i++)
        #pragma unroll
        for (int j = 0; j < 8; j++) {
            acc[i][j][0]=0.f; acc[i][j][1]=0.f; acc[i][j][2]=0.f; acc[i][j][3]=0.f;
        }

    int nk = kLen >> 5;
    #pragma unroll
    for (int i = 0; i < 8; i++) cp16(dstA0 + i*4096u, srcA0 + (size_t)i*32*lda);
    #pragma unroll
    for (int i = 0; i < 4; i++) cp16(dstB0 + i*4352u, srcB0 + (size_t)i*8*ldb);
    asm volatile("cp.async.commit_group;");
    asm volatile("cp.async.wait_group 0;");
    __syncthreads();

    for (int kt = 0; kt < nk; kt++) {
        int cur = kt & 1;
        if (kt + 1 < nk) {
            int k0 = (kt + 1) << 5;
            uint32_t abuf = dstA0 + (cur ^ 1)*32768u;
            const float* asrc = srcA0 + k0;
            #pragma unroll
            for (int i = 0; i < 8; i++) cp16(abuf + i*4096u, asrc + (size_t)i*32*lda);
            uint32_t bbuf = dstB0 + (cur ^ 1)*17408u;
            const float* bsrc = srcB0 + (size_t)k0*ldb;
            #pragma unroll
            for (int i = 0; i < 4; i++) cp16(bbuf + i*4352u, bsrc + (size_t)i*8*ldb);
            asm volatile("cp.async.commit_group;");
        }

        uint32_t aB = baseA + cur*32768u;
        const uint32_t* bW = BsW + cur*4352 + baseB;

        #pragma unroll
        for (int ks = 0; ks < 4; ks++) {
            uint32_t af[4][4], bfr[8][2];
            uint32_t csw = (uint32_t)((((ks*2 + khalf) ^ sw) << 4));
            #pragma unroll
            for (int mt = 0; mt < 4; mt++) {
                uint32_t addr = aB + mt*2048u + csw;
                asm volatile(
                    "ldmatrix.sync.aligned.m8n8.x4.shared.b16 {%0,%1,%2,%3}, [%4];"
                    : "=r"(af[mt][0]), "=r"(af[mt][1]), "=r"(af[mt][2]), "=r"(af[mt][3])
                    : "r"(addr));
            }
            #pragma unroll
            for (int nt = 0; nt < 8; nt++) {
                bfr[nt][0] = bW[ks*1088 + nt*8];
                bfr[nt][1] = bW[ks*1088 + 544 + nt*8];
            }
            #pragma unroll
            for (int mt = 0; mt < 4; mt++)
                #pragma unroll
                for (int nt = 0; nt < 8; nt++)
                    asm volatile(
                        "mma.sync.aligned.m16n8k8.row.col.f32.tf32.tf32.f32 "
                        "{%0,%1,%2,%3}, {%4,%5,%6,%7}, {%8,%9}, {%0,%1,%2,%3};"
                        : "+f"(acc[mt][nt][0]), "+f"(acc[mt][nt][1]),
                          "+f"(acc[mt][nt][2]), "+f"(acc[mt][nt][3])
                        : "r"(af[mt][0]), "r"(af[mt][1]),
                          "r"(af[mt][2]), "r"(af[mt][3]),
                          "r"(bfr[nt][0]), "r"(bfr[nt][1]));
        }

        if (kt + 1 < nk) {
            asm volatile("cp.async.wait_group 0;");
            __syncthreads();
        }
    }

    #pragma unroll
    for (int mt = 0; mt < 4; mt++) {
        int row0 = m0 + wm0 + mt*16 + (lane >> 2);
        #pragma unroll
        for (int nt = 0; nt < 8; nt++) {
            int col = n0 + wn0 + nt*8 + 2*(lane & 3);
            #pragma unroll
            for (int h = 0; h < 2; h++) {
                int rw = row0 + h*8;
                float v0 = acc[mt][nt][h*2+0];
                float v1 = acc[mt][nt][h*2+1];
                if (col + 1 < N) {
                    if (bias) { v0 += bias[col]; v1 += bias[col+1]; }
                    if (act)  { v0 = gelu_f(v0); v1 = gelu_f(v1); }
                    if (roundOut) { v0 = tfr(v0); v1 = tfr(v1); }
                    float2 o; o.x = v0; o.y = v1;
                    *(float2*)&C[(size_t)rw*N + col] = o;
                } else if (col < N) {
                    if (bias) v0 += bias[col];
                    if (act)  v0 = gelu_f(v0);
                    if (roundOut) v0 = tfr(v0);
                    C[(size_t)rw*N + col] = v0;
                }
            }
        }
    }
}

// ---------------- flash attention, KV-split ---------------------
__global__ void __launch_bounds__(64)
k_flash(const float* __restrict__ Q, const float* __restrict__ Kp,
        const float* __restrict__ Vp, int lenK, int causal)
{
    __shared__ float Ks[64*32];
    __shared__ float Vs[64*32];
    __shared__ float pads[64];
    int bh = blockIdx.x;
    int b = bh / HH, h = bh % HH;
    int tid = threadIdx.x;
    int i = blockIdx.y*64 + tid;
    size_t qr = (size_t)(b*TT + i);

    const float scale = 0.17677669529663687f;
    float q[32];
    #pragma unroll
    for (int d = 0; d < 32; d++) q[d] = Q[qr*DD + h*32 + d] * scale;

    float m = -CUDART_INF_F, l = 0.0f, o[32];
    #pragma unroll
    for (int d = 0; d < 32; d++) o[d] = 0.0f;

    int tilesTotal = lenK / 64;
    int tps = tilesTotal / NSPLIT;
    int t0 = blockIdx.z * tps, t1 = t0 + tps;
    if (causal) { int need = blockIdx.y + 1; if (t1 > need) t1 = need; }

    for (int tIdx = t0; tIdx < t1; tIdx++) {
        int j0 = tIdx*64;
        for (int idx = tid; idx < 512; idx += 64) {
            int jj = idx >> 3, dq = (idx & 7) * 4;
            size_t row = (size_t)(b*lenK + j0 + jj);
            *(float4*)&Ks[jj*32 + dq] = *(const float4*)&Kp[row*DD + h*32 + dq];
            *(float4*)&Vs[jj*32 + dq] = *(const float4*)&Vp[row*DD + h*32 + dq];
        }
        if (causal) pads[tid] = g_padbuf[b*TT + j0 + tid];
        __syncthreads();

        #pragma unroll 1
        for (int jj = 0; jj < 64; jj++) {
            int j = j0 + jj;
            if (causal && (j > i || pads[jj] == 0.0f)) continue;
            const float* kr = &Ks[jj*32];
            float s = 0.0f;
            #pragma unroll
            for (int d = 0; d < 32; d++) s += q[d]*kr[d];
            float mn = fmaxf(m, s);
            float corr = __expf(m - mn);
            float p = __expf(s - mn);
            l = l*corr + p;
            const float* vr = &Vs[jj*32];
            #pragma unroll
            for (int d = 0; d < 32; d++) o[d] = o[d]*corr + p*vr[d];
            m = mn;
        }
        __syncthreads();
    }

    size_t base = (size_t)blockIdx.z*QH + (size_t)bh*TT + i;
    g_scratch[O_PM + base] = m;
    g_scratch[O_PL + base] = l;
    #pragma unroll
    for (int d = 0; d < 32; d++)
        g_scratch[O_PO + base*32 + d] = o[d];
}

__global__ void k_fmerge(float* __restrict__ O)
{
    int idx = blockIdx.x*256 + threadIdx.x;
    int qh = idx >> 5, d = idx & 31;
    float M = -CUDART_INF_F;
    #pragma unroll
    for (int s = 0; s < NSPLIT; s++)
        M = fmaxf(M, g_scratch[O_PM + (size_t)s*QH + qh]);
    float L = 0.0f, acc = 0.0f;
    #pragma unroll
    for (int s = 0; s < NSPLIT; s++) {
        size_t base = (size_t)s*QH + qh;
        float w = __expf(g_scratch[O_PM + base] - M);
        L   += w * g_scratch[O_PL + base];
        acc += w * g_scratch[O_PO + base*32 + d];
    }
    int bh = qh / TT, i = qh % TT;
    int b = bh / HH, h = bh % HH;
    O[(size_t)(b*TT + i)*DD + h*32 + d] = tfr(acc / L);
}

// ---------------- fused residual-add + LayerNorm -------------------------
__device__ __forceinline__ void addln_core(float v, int r, int d,
        const float* g, const float* be, float* Y)
{
    __shared__ float sh[18];
    float s1 = v, s2 = v*v;
    #pragma unroll
    for (int off = 16; off; off >>= 1) {
        s1 += __shfl_down_sync(0xFFFFFFFFu, s1, off);
        s2 += __shfl_down_sync(0xFFFFFFFFu, s2, off);
    }
    int warp = d >> 5, lane = d & 31;
    if (lane == 0) { sh[warp] = s1; sh[8 + warp] = s2; }
    __syncthreads();
    if (d == 0) {
        float t1 = 0.f, t2 = 0.f;
        for (int w = 0; w < 8; w++) { t1 += sh[w]; t2 += sh[8 + w]; }
        float mean = t1 * (1.0f/256.0f);
        float var  = t2 * (1.0f/256.0f) - mean*mean;
        sh[16] = mean;
        sh[17] = rsqrtf(var + 1e-5f);
    }
    __syncthreads();
    Y[(size_t)r*DD + d] = tfr((v - sh[16])*sh[17]*g[d] + be[d]);
}

__global__ void k_addln(const float* __restrict__ X, const float* __restrict__ A,
                        const float* __restrict__ g, const float* __restrict__ be,
                        float* __restrict__ Y)
{
    int r = blockIdx.x, d = threadIdx.x;
    float v = X[(size_t)r*DD + d] + A[(size_t)r*DD + d];
    addln_core(v, r, d, g, be, Y);
}

// x + b + sum of 4 split-K partials (stride SLAB), then LN
__global__ void k_addln4(const float* __restrict__ X, const float* __restrict__ P,
                         const float* __restrict__ bias,
                         const float* __restrict__ g, const float* __restrict__ be,
                         float* __restrict__ Y)
{
    int r = blockIdx.x, d = threadIdx.x;
    size_t off = (size_t)r*DD + d;
    float v = X[off] + bias[d] + P[off] + P[off + SLAB] + P[off + 2*SLAB] + P[off + 3*SLAB];
    addln_core(v, r, d, g, be, Y);
}

// ---------------- host orchestration -------------------------------------
extern "C" void kernel_launch(void* const* d_in, const int* in_sizes, int n_in,
                              void* d_out, int out_size)
{
    const int*   src   = (const int*)  d_in[0];
    const int*   tgt   = (const int*)  d_in[1];
    const float* enc   = (const float*)d_in[2];
    const float* emb   = (const float*)d_in[3];
    const float* Wq_s  = (const float*)d_in[4];
    const float* Wk_s  = (const float*)d_in[5];
    const float* Wv_s  = (const float*)d_in[6];
    const float* Wo_s  = (const float*)d_in[7];
    const float* bo_s  = (const float*)d_in[8];
    const float* Wq_c  = (const float*)d_in[9];
    const float* Wk_c  = (const float*)d_in[10];
    const float* Wv_c  = (const float*)d_in[11];
    const float* Wo_c  = (const float*)d_in[12];
    const float* bo_c  = (const float*)d_in[13];
    const float* W1    = (const float*)d_in[14];
    const float* b1    = (const float*)d_in[15];
    const float* W2    = (const float*)d_in[16];
    const float* b2    = (const float*)d_in[17];
    const float* g1    = (const float*)d_in[18];
    const float* be1   = (const float*)d_in[19];
    const float* g2    = (const float*)d_in[20];
    const float* be2   = (const float*)d_in[21];
    const float* g3    = (const float*)d_in[22];
    const float* be3   = (const float*)d_in[23];
    const float* Wf    = (const float*)d_in[24];
    const float* bf    = (const float*)d_in[25];
    float* out = (float*)d_out;

    float* s = nullptr;
    cudaGetSymbolAddress((void**)&s, g_scratch);
    float* x0   = s + O_X0;
    float* x1   = s + O_X1;
    float* x2   = s + O_X2;
    float* x3   = s + O_X3;
    float* q    = s + O_Q;
    float* k    = s + O_K;
    float* v    = s + O_V;
    float* att  = s + O_ATT;
    float* proj = s + O_PROJ;
    float* encz = s + O_ENCZ;
    float* ff   = s + O_FF;
    float* wqs  = s + O_WATT + 0*65536;
    float* wks  = s + O_WATT + 1*65536;
    float* wvs  = s + O_WATT + 2*65536;
    float* wos  = s + O_WATT + 3*65536;
    float* wqc  = s + O_WATT + 4*65536;
    float* wkc  = s + O_WATT + 5*65536;
    float* wvc  = s + O_WATT + 6*65536;
    float* woc  = s + O_WATT + 7*65536;
    float* w1c  = s + O_W1;
    float* w2c  = s + O_W2;
    float* wfc  = s + O_WF;

    long long logitsN = (long long)BT * VOC;
    int write_ids = ((long long)out_size >= logitsN + BT);
    float* out_ids = out + logitsN;

    cudaFuncSetAttribute(k_mma,    cudaFuncAttributeMaxDynamicSharedMemorySize, SMEM_GEMM_BYTES);
    cudaFuncSetAttribute(k_mma3,   cudaFuncAttributeMaxDynamicSharedMemorySize, SMEM_GEMM_BYTES);
    cudaFuncSetAttribute(k_mma256, cudaFuncAttributeMaxDynamicSharedMemorySize, SMEM_G256);

    auto gg = [](int M, int N) { return dim3((unsigned)((N + 127) / 128), (unsigned)(M / 128)); };

    // weight prep (tf32 RNA) + embeddings
    k_prep8<<<2048, 256>>>(Wq_s, Wk_s, Wv_s, Wo_s, Wq_c, Wk_c, Wv_c, Wo_c);
    k_conv<<<2048, 256>>>(W1, w1c, 524288);
    k_conv<<<2048, 256>>>(W2, w2c, 524288);
    k_convpad<<<dim3(199, 256), 128>>>(Wf);
    k_embed<<<BT, 256>>>(tgt, emb, out_ids, write_ids);
    k_encz <<<BB*SS, 256>>>(src, enc);

    // --- self attention ---
    k_mma3<<<dim3(2, 32, 3), 256, SMEM_GEMM_BYTES>>>(x0, x0, x0, wqs, wks, wvs, q, k, v, BT);
    k_flash<<<dim3(BB*HH, TT/64, NSPLIT), 64>>>(q, k, v, TT, 1);
    k_fmerge<<<QH*32/256, 256>>>(att);
    k_mma<<<gg(BT, DD), 256, SMEM_GEMM_BYTES>>>(att, wos, bo_s, proj, BT, DD, DD, DD, 0, 0);
    k_addln<<<BT, 256>>>(x0, proj, g1, be1, x1);

    // --- cross attention ---
    k_mma3<<<dim3(2, 32, 3), 256, SMEM_GEMM_BYTES>>>(x1, encz, encz, wqc, wkc, wvc, q, k, v, BT);
    k_flash<<<dim3(BB*HH, TT/64, NSPLIT), 64>>>(q, k, v, SS, 0);
    k_fmerge<<<QH*32/256, 256>>>(att);
    k_mma<<<gg(BT, DD), 256, SMEM_GEMM_BYTES>>>(att, woc, bo_c, proj, BT, DD, DD, DD, 0, 0);
    k_addln<<<BT, 256>>>(x1, proj, g2, be2, x2);

    // --- feed forward (big-tile GEMMs) ---
    // FFN1: [4096,256] x [256,2048], gelu+round fused
    k_mma256<<<dim3(16, 16, 1), 256, SMEM_G256>>>(x2, w1c, b1, ff,
                                                  BT, FFD, DD, FFD, DD, 0, 1, 1);
    // FFN2: split-K x4 (kLen=512), partials into q..att slabs (stride SLAB)
    k_mma256<<<dim3(2, 16, 4), 256, SMEM_G256>>>(ff, w2c, nullptr, q,
                                                 BT, DD, FFD, DD, FFD/4, SLAB, 0, 0);
    k_addln4<<<BT, 256>>>(x2, q, b2, g3, be3, x3);

    // --- vocab projection into d_out (big-tile) ---
    k_mma256<<<dim3(199, 16, 1), 256, SMEM_G256>>>(x3, wfc, bf, out,
                                                   BT, VOC, DD, VOCP, DD, 0, 0, 0);
}

// round 13
// speedup vs baseline: 1.2013x; 1.2013x over previous
#include <cuda_runtime.h>
#include <cuda_fp16.h>
#include <math.h>
#include <math_constants.h>
#include <stdint.h>

#define BB 2
#define TT 2048
#define SS 2048
#define DD 256
#define HH 8
#define FFD 2048
#define VOC 25426
#define VOCP 25472              // padded vocab (199*128)
#define BT (BB*TT)
#define QH (BB*HH*TT)
#define NSPLIT 8

// ---------------- scratch ----------------
#define SLAB 1048576
#define O_X0   (0*SLAB)
#define O_X1   (1*SLAB)
#define O_X2   (2*SLAB)
#define O_X3   (3*SLAB)
#define O_Q    (4*SLAB)
#define O_K    (5*SLAB)
#define O_V    (6*SLAB)
#define O_ATT  (7*SLAB)
#define O_PROJ (8*SLAB)
#define O_ENCZ (9*SLAB)
#define O_FF   ((size_t)10*SLAB)                 // ff halves: 4 slabs
#define O_PO   ((size_t)18*SLAB)
#define O_PM   ((size_t)26*SLAB)
#define O_PL   ((size_t)26*SLAB + NSPLIT*QH)
#define O_WH   ((size_t)27*SLAB)                 // 8 att weights fp16 [256][256]
#define O_W1H  (O_WH  + 8*32768)
#define O_W2H  (O_W1H + 262144)
#define O_WFH  (O_W2H + 262144)                  // [VOCP][256] fp16
#define SCRATCH_FLOATS ((size_t)35*SLAB)

__device__ float g_scratch[SCRATCH_FLOATS];
__device__ float g_padbuf[BT];

__device__ __forceinline__ float gelu_f(float v) {
    return 0.5f*v*(1.0f + erff(v*0.70710678118654752f));
}
__device__ __forceinline__ void cp16(uint32_t dst, const void* src) {
    asm volatile("cp.async.cg.shared.global [%0], [%1], 16;" :: "r"(dst), "l"(src));
}

// ---------------- weight prep: fp32 [K][N] -> fp16 [Npad][K] -----------
__global__ void k_transp(const float* __restrict__ src, __half* __restrict__ dst,
                         int K, int N)
{
    __shared__ float t[32][33];
    int n0 = blockIdx.x*32, k0 = blockIdx.y*32;
    int tx = threadIdx.x, ty = threadIdx.y;
    #pragma unroll
    for (int j = 0; j < 4; j++) {
        int k = k0 + ty + j*8, n = n0 + tx;
        t[ty + j*8][tx] = (n < N) ? src[(size_t)k*N + n] : 0.0f;
    }
    __syncthreads();
    #pragma unroll
    for (int j = 0; j < 4; j++) {
        int n = n0 + ty + j*8, k = k0 + tx;
        dst[(size_t)n*K + k] = __float2half(t[tx][ty + j*8]);
    }
}

__global__ void k_transpW8(const float* w0, const float* w1, const float* w2, const float* w3,
                           const float* w4, const float* w5, const float* w6, const float* w7,
                           __half* __restrict__ dst)
{
    __shared__ float t[32][33];
    const float* src;
    switch (blockIdx.z) {
        case 0: src = w0; break; case 1: src = w1; break;
        case 2: src = w2; break; case 3: src = w3; break;
        case 4: src = w4; break; case 5: src = w5; break;
        case 6: src = w6; break; default: src = w7; break;
    }
    __half* d = dst + (size_t)blockIdx.z*65536;
    int n0 = blockIdx.x*32, k0 = blockIdx.y*32;
    int tx = threadIdx.x, ty = threadIdx.y;
    #pragma unroll
    for (int j = 0; j < 4; j++)
        t[ty + j*8][tx] = src[(size_t)(k0 + ty + j*8)*256 + n0 + tx];
    __syncthreads();
    #pragma unroll
    for (int j = 0; j < 4; j++)
        d[(size_t)(n0 + ty + j*8)*256 + k0 + tx] = __float2half(t[tx][ty + j*8]);
}

// ---------------- embedding + positional encoding ----------------
__global__ void k_embed(const int* __restrict__ tgt_in,
                        const float* __restrict__ emb,
                        __half* __restrict__ X,
                        float* __restrict__ out_ids, int write_ids)
{
    int r = blockIdx.x;
    int d = threadIdx.x;
    int b = r / TT, t = r % TT;
    int id = (t == 0) ? VOC : tgt_in[b*(TT-1) + (t-1)];
    if (d == 0) {
        g_padbuf[r] = (id != 0) ? 1.0f : 0.0f;
        if (write_ids) out_ids[r] = (t == 0) ? 0.0f : (float)id;
    }
    int i2 = d & ~1;
    float div = __expf(-(float)i2 * (9.210340371976184f / 256.0f));
    float ang = (float)t * div;
    float pe  = (d & 1) ? cosf(ang) : sinf(ang);
    X[(size_t)r*DD + d] = __float2half(2.0f*emb[(size_t)id*DD + d] + pe);
}

__global__ void k_encz(const int* __restrict__ src, const float* __restrict__ enc,
                       __half* __restrict__ E)
{
    int r = blockIdx.x;
    int d = threadIdx.x;
    E[(size_t)r*DD + d] = __float2half((src[r] != 0) ? enc[(size_t)r*DD + d] : 0.0f);
}

// ================= fp16 mma.sync GEMM (m16n8k16) ==========================
// C[M,N] = A[M,K] @ B^T  where B is stored [N][K] fp16 (K contiguous).
// CTA 128x128, BK=32, 8 warps (2m x 4n), warp tile 64x32.
// smem rows padded to 40 halves (80B) -> conflict-free ldmatrix.
// flags: bit0 = gelu, bit1 = fp16 output.
#define HTILE 10240           // 128*80 bytes
#define HSTAGE (2*HTILE)

__device__ __forceinline__ void hgemm_core(
    const __half* __restrict__ A, const __half* __restrict__ Bm,
    const float* __restrict__ bias, void* Cv,
    int M, int N, int K, int flags, char* sm)
{
    uint32_t sb = (uint32_t)__cvta_generic_to_shared(sm);
    int tid = threadIdx.x;
    int lane = tid & 31, warp = tid >> 5;
    int wm0 = (warp >> 2) * 64, wn0 = (warp & 3) * 32;
    int m0 = blockIdx.y * 128, n0 = blockIdx.x * 128;

    // cp.async: 512 16B chunks per operand; 2 chunks each per thread
    int r0 = tid >> 2, c0 = tid & 3;               // idx = tid
    int r1 = (tid + 256) >> 2, c1 = tid & 3;       // idx = tid+256

    const __half* srcA = A + (size_t)m0*K;
    const __half* srcB = Bm + (size_t)n0*K;

    // frag bases
    uint32_t aBase = sb + (uint32_t)((wm0 + (lane & 15))*80 + (lane >> 4)*16);
    uint32_t bBase = sb + 10240u + (uint32_t)((wn0 + (lane & 15))*80 + (lane >> 4)*16);

    float acc[4][4][4];
    #pragma unroll
    for (int i = 0; i < 4; i++)
        #pragma unroll
        for (int j = 0; j < 4; j++) {
            acc[i][j][0]=0.f; acc[i][j][1]=0.f; acc[i][j][2]=0.f; acc[i][j][3]=0.f;
        }

    int nk = K >> 5;

    // prologue: tile 0 -> stage 0
    {
        uint32_t st = sb;
        cp16(st + (uint32_t)(r0*80 + c0*16),           srcA + (size_t)r0*K + c0*8);
        cp16(st + (uint32_t)(r1*80 + c1*16),           srcA + (size_t)r1*K + c1*8);
        cp16(st + 10240u + (uint32_t)(r0*80 + c0*16),  srcB + (size_t)r0*K + c0*8);
        cp16(st + 10240u + (uint32_t)(r1*80 + c1*16),  srcB + (size_t)r1*K + c1*8);
        asm volatile("cp.async.commit_group;");
        asm volatile("cp.async.wait_group 0;");
    }
    __syncthreads();

    for (int kt = 0; kt < nk; kt++) {
        int cur = kt & 1;
        if (kt + 1 < nk) {
            int k0 = (kt + 1) << 5;
            uint32_t st = sb + (uint32_t)(cur ^ 1)*HSTAGE;
            cp16(st + (uint32_t)(r0*80 + c0*16),          srcA + (size_t)r0*K + k0 + c0*8);
            cp16(st + (uint32_t)(r1*80 + c1*16),          srcA + (size_t)r1*K + k0 + c1*8);
            cp16(st + 10240u + (uint32_t)(r0*80 + c0*16), srcB + (size_t)r0*K + k0 + c0*8);
            cp16(st + 10240u + (uint32_t)(r1*80 + c1*16), srcB + (size_t)r1*K + k0 + c1*8);
            asm volatile("cp.async.commit_group;");
        }

        uint32_t aB = aBase + (uint32_t)cur*HSTAGE;
        uint32_t bB = bBase + (uint32_t)cur*HSTAGE;

        #pragma unroll
        for (int ks = 0; ks < 2; ks++) {
            uint32_t af[4][4], bf2[2][4];
            #pragma unroll
            for (int mt = 0; mt < 4; mt++) {
                uint32_t addr = aB + (uint32_t)(mt*16*80 + ks*32);
                asm volatile(
                    "ldmatrix.sync.aligned.m8n8.x4.shared.b16 {%0,%1,%2,%3}, [%4];"
                    : "=r"(af[mt][0]), "=r"(af[mt][1]), "=r"(af[mt][2]), "=r"(af[mt][3])
                    : "r"(addr));
            }
            #pragma unroll
            for (int nt16 = 0; nt16 < 2; nt16++) {
                uint32_t addr = bB + (uint32_t)(nt16*16*80 + ks*32);
                asm volatile(
                    "ldmatrix.sync.aligned.m8n8.x4.shared.b16 {%0,%1,%2,%3}, [%4];"
                    : "=r"(bf2[nt16][0]), "=r"(bf2[nt16][1]),
                      "=r"(bf2[nt16][2]), "=r"(bf2[nt16][3])
                    : "r"(addr));
            }
            #pragma unroll
            for (int mt = 0; mt < 4; mt++)
                #pragma unroll
                for (int nt = 0; nt < 4; nt++) {
                    uint32_t b0 = bf2[nt >> 1][nt & 1];
                    uint32_t b1 = bf2[nt >> 1][(nt & 1) + 2];
                    asm volatile(
                        "mma.sync.aligned.m16n8k16.row.col.f32.f16.f16.f32 "
                        "{%0,%1,%2,%3}, {%4,%5,%6,%7}, {%8,%9}, {%0,%1,%2,%3};"
                        : "+f"(acc[mt][nt][0]), "+f"(acc[mt][nt][1]),
                          "+f"(acc[mt][nt][2]), "+f"(acc[mt][nt][3])
                        : "r"(af[mt][0]), "r"(af[mt][1]),
                          "r"(af[mt][2]), "r"(af[mt][3]),
                          "r"(b0), "r"(b1));
                }
        }

        if (kt + 1 < nk) {
            asm volatile("cp.async.wait_group 0;");
            __syncthreads();
        }
    }

    int doGelu = flags & 1, outHalf = flags & 2;
    #pragma unroll
    for (int mt = 0; mt < 4; mt++) {
        int row0 = m0 + wm0 + mt*16 + (lane >> 2);
        #pragma unroll
        for (int nt = 0; nt < 4; nt++) {
            int col = n0 + wn0 + nt*8 + 2*(lane & 3);
            #pragma unroll
            for (int h = 0; h < 2; h++) {
                int rw = row0 + h*8;
                float v0 = acc[mt][nt][h*2+0];
                float v1 = acc[mt][nt][h*2+1];
                if (col + 1 < N) {
                    if (bias)  { v0 += bias[col]; v1 += bias[col+1]; }
                    if (doGelu){ v0 = gelu_f(v0); v1 = gelu_f(v1); }
                    if (outHalf) {
                        __half2 o; o.x = __float2half(v0); o.y = __float2half(v1);
                        *(__half2*)&((__half*)Cv)[(size_t)rw*N + col] = o;
                    } else {
                        float2 o; o.x = v0; o.y = v1;
                        *(float2*)&((float*)Cv)[(size_t)rw*N + col] = o;
                    }
                } else if (col < N) {
                    if (bias)  v0 += bias[col];
                    if (doGelu) v0 = gelu_f(v0);
                    if (outHalf) ((__half*)Cv)[(size_t)rw*N + col] = __float2half(v0);
                    else         ((float*)Cv)[(size_t)rw*N + col] = v0;
                }
            }
        }
    }
}

__global__ void __launch_bounds__(256)
k_hgemm(const __half* __restrict__ A, const __half* __restrict__ Bm,
        const float* __restrict__ bias, void* Cv, int M, int N, int K, int flags)
{
    __shared__ __align__(128) char sm[2*HSTAGE];
    hgemm_core(A, Bm, bias, Cv, M, N, K, flags, sm);
}

// fused QKV: blockIdx.z selects (A, W, C); N=K=256, fp32 out, no bias
__global__ void __launch_bounds__(256)
k_hgemm3(const __half* a0, const __half* a1, const __half* a2,
         const __half* w0, const __half* w1, const __half* w2,
         float* c0, float* c1, float* c2)
{
    __shared__ __align__(128) char sm[2*HSTAGE];
    const __half* A; const __half* W; float* C;
    if (blockIdx.z == 0)      { A = a0; W = w0; C = c0; }
    else if (blockIdx.z == 1) { A = a1; W = w1; C = c1; }
    else                      { A = a2; W = w2; C = c2; }
    hgemm_core(A, W, nullptr, C, BT, DD, DD, 0, sm);
}

// ---------------- flash attention, KV-split (fp32 q/k/v) ------------------
__global__ void __launch_bounds__(64)
k_flash(const float* __restrict__ Q, const float* __restrict__ Kp,
        const float* __restrict__ Vp, int lenK, int causal)
{
    __shared__ float Ks[64*32];
    __shared__ float Vs[64*32];
    __shared__ float pads[64];
    int bh = blockIdx.x;
    int b = bh / HH, h = bh % HH;
    int tid = threadIdx.x;
    int i = blockIdx.y*64 + tid;
    size_t qr = (size_t)(b*TT + i);

    const float scale = 0.17677669529663687f;
    float q[32];
    #pragma unroll
    for (int d = 0; d < 32; d++) q[d] = Q[qr*DD + h*32 + d] * scale;

    float m = -CUDART_INF_F, l = 0.0f, o[32];
    #pragma unroll
    for (int d = 0; d < 32; d++) o[d] = 0.0f;

    int tilesTotal = lenK / 64;
    int tps = tilesTotal / NSPLIT;
    int t0 = blockIdx.z * tps, t1 = t0 + tps;
    if (causal) { int need = blockIdx.y + 1; if (t1 > need) t1 = need; }

    for (int tIdx = t0; tIdx < t1; tIdx++) {
        int j0 = tIdx*64;
        for (int idx = tid; idx < 512; idx += 64) {
            int jj = idx >> 3, dq = (idx & 7) * 4;
            size_t row = (size_t)(b*lenK + j0 + jj);
            *(float4*)&Ks[jj*32 + dq] = *(const float4*)&Kp[row*DD + h*32 + dq];
            *(float4*)&Vs[jj*32 + dq] = *(const float4*)&Vp[row*DD + h*32 + dq];
        }
        if (causal) pads[tid] = g_padbuf[b*TT + j0 + tid];
        __syncthreads();

        #pragma unroll 1
        for (int jj = 0; jj < 64; jj++) {
            int j = j0 + jj;
            if (causal && (j > i || pads[jj] == 0.0f)) continue;
            const float* kr = &Ks[jj*32];
            float s = 0.0f;
            #pragma unroll
            for (int d = 0; d < 32; d++) s += q[d]*kr[d];
            float mn = fmaxf(m, s);
            float corr = __expf(m - mn);
            float p = __expf(s - mn);
            l = l*corr + p;
            const float* vr = &Vs[jj*32];
            #pragma unroll
            for (int d = 0; d < 32; d++) o[d] = o[d]*corr + p*vr[d];
            m = mn;
        }
        __syncthreads();
    }

    size_t base = (size_t)blockIdx.z*QH + (size_t)bh*TT + i;
    g_scratch[O_PM + base] = m;
    g_scratch[O_PL + base] = l;
    #pragma unroll
    for (int d = 0; d < 32; d++)
        g_scratch[O_PO + base*32 + d] = o[d];
}

__global__ void k_fmerge(__half* __restrict__ O)
{
    int idx = blockIdx.x*256 + threadIdx.x;
    int qh = idx >> 5, d = idx & 31;
    float M = -CUDART_INF_F;
    #pragma unroll
    for (int s = 0; s < NSPLIT; s++)
        M = fmaxf(M, g_scratch[O_PM + (size_t)s*QH + qh]);
    float L = 0.0f, acc = 0.0f;
    #pragma unroll
    for (int s = 0; s < NSPLIT; s++) {
        size_t base = (size_t)s*QH + qh;
        float w = __expf(g_scratch[O_PM + base] - M);
        L   += w * g_scratch[O_PL + base];
        acc += w * g_scratch[O_PO + base*32 + d];
    }
    int bh = qh / TT, i = qh % TT;
    int b = bh / HH, h = bh % HH;
    O[(size_t)(b*TT + i)*DD + h*32 + d] = __float2half(acc / L);
}

// ---------------- fused residual-add + LayerNorm -------------------------
__global__ void k_addln(const __half* __restrict__ X, const float* __restrict__ A,
                        const float* __restrict__ g, const float* __restrict__ be,
                        __half* __restrict__ Y)
{
    int r = blockIdx.x, d = threadIdx.x;
    float v = __half2float(X[(size_t)r*DD + d]) + A[(size_t)r*DD + d];
    __shared__ float sh[18];
    float s1 = v, s2 = v*v;
    #pragma unroll
    for (int off = 16; off; off >>= 1) {
        s1 += __shfl_down_sync(0xFFFFFFFFu, s1, off);
        s2 += __shfl_down_sync(0xFFFFFFFFu, s2, off);
    }
    int warp = d >> 5, lane = d & 31;
    if (lane == 0) { sh[warp] = s1; sh[8 + warp] = s2; }
    __syncthreads();
    if (d == 0) {
        float t1 = 0.f, t2 = 0.f;
        for (int w = 0; w < 8; w++) { t1 += sh[w]; t2 += sh[8 + w]; }
        float mean = t1 * (1.0f/256.0f);
        float var  = t2 * (1.0f/256.0f) - mean*mean;
        sh[16] = mean;
        sh[17] = rsqrtf(var + 1e-5f);
    }
    __syncthreads();
    Y[(size_t)r*DD + d] = __float2half((v - sh[16])*sh[17]*g[d] + be[d]);
}

// ---------------- host orchestration -------------------------------------
extern "C" void kernel_launch(void* const* d_in, const int* in_sizes, int n_in,
                              void* d_out, int out_size)
{
    const int*   src   = (const int*)  d_in[0];
    const int*   tgt   = (const int*)  d_in[1];
    const float* enc   = (const float*)d_in[2];
    const float* emb   = (const float*)d_in[3];
    const float* Wq_s  = (const float*)d_in[4];
    const float* Wk_s  = (const float*)d_in[5];
    const float* Wv_s  = (const float*)d_in[6];
    const float* Wo_s  = (const float*)d_in[7];
    const float* bo_s  = (const float*)d_in[8];
    const float* Wq_c  = (const float*)d_in[9];
    const float* Wk_c  = (const float*)d_in[10];
    const float* Wv_c  = (const float*)d_in[11];
    const float* Wo_c  = (const float*)d_in[12];
    const float* bo_c  = (const float*)d_in[13];
    const float* W1    = (const float*)d_in[14];
    const float* b1    = (const float*)d_in[15];
    const float* W2    = (const float*)d_in[16];
    const float* b2    = (const float*)d_in[17];
    const float* g1    = (const float*)d_in[18];
    const float* be1   = (const float*)d_in[19];
    const float* g2    = (const float*)d_in[20];
    const float* be2   = (const float*)d_in[21];
    const float* g3    = (const float*)d_in[22];
    const float* be3   = (const float*)d_in[23];
    const float* Wf    = (const float*)d_in[24];
    const float* bf    = (const float*)d_in[25];
    float* out = (float*)d_out;

    float* s = nullptr;
    cudaGetSymbolAddress((void**)&s, g_scratch);
    __half* x0h  = (__half*)(s + O_X0);
    __half* x1h  = (__half*)(s + O_X1);
    __half* x2h  = (__half*)(s + O_X2);
    __half* x3h  = (__half*)(s + O_X3);
    float*  q    = s + O_Q;
    float*  k    = s + O_K;
    float*  v    = s + O_V;
    __half* atth = (__half*)(s + O_ATT);
    float*  proj = s + O_PROJ;
    __half* ench = (__half*)(s + O_ENCZ);
    __half* ffh  = (__half*)(s + O_FF);
    __half* whA  = (__half*)(s + O_WH);          // 8 x [256][256]
    __half* w1h  = (__half*)(s + O_W1H);         // [2048][256]
    __half* w2h  = (__half*)(s + O_W2H);         // [256][2048]
    __half* wfh  = (__half*)(s + O_WFH);         // [VOCP][256]

    __half* wqs = whA + 0*65536;
    __half* wks = whA + 1*65536;
    __half* wvs = whA + 2*65536;
    __half* wos = whA + 3*65536;
    __half* wqc = whA + 4*65536;
    __half* wkc = whA + 5*65536;
    __half* wvc = whA + 6*65536;
    __half* woc = whA + 7*65536;

    long long logitsN = (long long)BT * VOC;
    int write_ids = ((long long)out_size >= logitsN + BT);
    float* out_ids = out + logitsN;

    dim3 t32x8(32, 8);

    // ---- weight prep (fp16, transposed to [N][K]) + embeddings ----
    k_transpW8<<<dim3(8, 8, 8), t32x8>>>(Wq_s, Wk_s, Wv_s, Wo_s, Wq_c, Wk_c, Wv_c, Wo_c, whA);
    k_transp<<<dim3(FFD/32, DD/32),  t32x8>>>(W1, w1h, DD, FFD);
    k_transp<<<dim3(DD/32,  FFD/32), t32x8>>>(W2, w2h, FFD, DD);
    k_transp<<<dim3(VOCP/32, DD/32), t32x8>>>(Wf, wfh, DD, VOC);
    k_embed<<<BT, 256>>>(tgt, emb, x0h, out_ids, write_ids);
    k_encz <<<BB*SS, 256>>>(src, enc, ench);

    // ---- self attention ----
    k_hgemm3<<<dim3(2, 32, 3), 256>>>(x0h, x0h, x0h, wqs, wks, wvs, q, k, v);
    k_flash<<<dim3(BB*HH, TT/64, NSPLIT), 64>>>(q, k, v, TT, 1);
    k_fmerge<<<QH*32/256, 256>>>(atth);
    k_hgemm<<<dim3(2, 32), 256>>>(atth, wos, bo_s, proj, BT, DD, DD, 0);
    k_addln<<<BT, 256>>>(x0h, proj, g1, be1, x1h);

    // ---- cross attention ----
    k_hgemm3<<<dim3(2, 32, 3), 256>>>(x1h, ench, ench, wqc, wkc, wvc, q, k, v);
    k_flash<<<dim3(BB*HH, TT/64, NSPLIT), 64>>>(q, k, v, SS, 0);
    k_fmerge<<<QH*32/256, 256>>>(atth);
    k_hgemm<<<dim3(2, 32), 256>>>(atth, woc, bo_c, proj, BT, DD, DD, 0);
    k_addln<<<BT, 256>>>(x1h, proj, g2, be2, x2h);

    // ---- feed forward ----
    k_hgemm<<<dim3(16, 32), 256>>>(x2h, w1h, b1, ffh, BT, FFD, DD, 3);   // gelu + fp16 out
    k_hgemm<<<dim3(2, 32),  256>>>(ffh, w2h, b2, proj, BT, DD, FFD, 0);
    k_addln<<<BT, 256>>>(x2h, proj, g3, be3, x3h);

    // ---- vocab projection into d_out ----
    k_hgemm<<<dim3(VOCP/128, 32), 256>>>(x3h, wfh, bf, out, BT, VOC, DD, 0);
}

// round 15
// speedup vs baseline: 2.5041x; 2.0845x over previous
#include <cuda_runtime.h>
#include <cuda_fp16.h>
#include <math.h>
#include <math_constants.h>
#include <stdint.h>

#define BB 2
#define TT 2048
#define SS 2048
#define DD 256
#define HH 8
#define FFD 2048
#define VOC 25426
#define VOCP 25472              // padded vocab (199*128)
#define BT (BB*TT)
#define QH (BB*HH*TT)
#define NSPLIT 4

// ---------------- scratch ----------------
#define SLAB 1048576
#define O_X0   (0*SLAB)
#define O_X1   (1*SLAB)
#define O_X2   (2*SLAB)
#define O_X3   (3*SLAB)
#define O_Q    (4*SLAB)
#define O_K    (5*SLAB)
#define O_V    (6*SLAB)
#define O_ATT  (7*SLAB)
#define O_PROJ (8*SLAB)
#define O_ENCZ (9*SLAB)
#define O_FF   ((size_t)10*SLAB)
#define O_PO   ((size_t)18*SLAB)                 // NSPLIT*QH*32 = 4 slabs
#define O_PM   ((size_t)26*SLAB)
#define O_PL   ((size_t)26*SLAB + NSPLIT*QH)
#define O_WH   ((size_t)27*SLAB)                 // 8 att weights fp16 [256][256]
#define O_W1H  (O_WH  + 8*32768)
#define O_W2H  (O_W1H + 262144)
#define O_WFH  (O_W2H + 262144)                  // [VOCP][256] fp16
#define SCRATCH_FLOATS ((size_t)35*SLAB)

__device__ float g_scratch[SCRATCH_FLOATS];
__device__ float g_padbuf[BT];

__device__ __forceinline__ float gelu_f(float v) {
    return 0.5f*v*(1.0f + erff(v*0.70710678118654752f));
}
__device__ __forceinline__ void cp16(uint32_t dst, const void* src) {
    asm volatile("cp.async.cg.shared.global [%0], [%1], 16;" :: "r"(dst), "l"(src));
}
#define HMMA(acc, a0, a1, a2, a3, b0, b1) \
    asm volatile( \
        "mma.sync.aligned.m16n8k16.row.col.f32.f16.f16.f32 " \
        "{%0,%1,%2,%3}, {%4,%5,%6,%7}, {%8,%9}, {%0,%1,%2,%3};" \
        : "+f"((acc)[0]), "+f"((acc)[1]), "+f"((acc)[2]), "+f"((acc)[3]) \
        : "r"(a0), "r"(a1), "r"(a2), "r"(a3), "r"(b0), "r"(b1))

__device__ __forceinline__ uint32_t packh2(float lo, float hi) {
    uint32_t u;
    asm("cvt.rn.f16x2.f32 %0, %1, %2;" : "=r"(u) : "f"(hi), "f"(lo));
    return u;
}

// ---------------- weight prep: fp32 [K][N] -> fp16 [Npad][K] -----------
__global__ void k_transp(const float* __restrict__ src, __half* __restrict__ dst,
                         int K, int N)
{
    __shared__ float t[32][33];
    int n0 = blockIdx.x*32, k0 = blockIdx.y*32;
    int tx = threadIdx.x, ty = threadIdx.y;
    #pragma unroll
    for (int j = 0; j < 4; j++) {
        int k = k0 + ty + j*8, n = n0 + tx;
        t[ty + j*8][tx] = (n < N) ? src[(size_t)k*N + n] : 0.0f;
    }
    __syncthreads();
    #pragma unroll
    for (int j = 0; j < 4; j++) {
        int n = n0 + ty + j*8, k = k0 + tx;
        dst[(size_t)n*K + k] = __float2half(t[tx][ty + j*8]);
    }
}

// att weights; Wq_s (idx 0) and Wq_c (idx 4) pre-scaled by 1/sqrt(32)
__global__ void k_transpW8(const float* w0, const float* w1, const float* w2, const float* w3,
                           const float* w4, const float* w5, const float* w6, const float* w7,
                           __half* __restrict__ dst)
{
    __shared__ float t[32][33];
    const float* src;
    switch (blockIdx.z) {
        case 0: src = w0; break; case 1: src = w1; break;
        case 2: src = w2; break; case 3: src = w3; break;
        case 4: src = w4; break; case 5: src = w5; break;
        case 6: src = w6; break; default: src = w7; break;
    }
    float sc = (blockIdx.z == 0 || blockIdx.z == 4) ? 0.17677669529663687f : 1.0f;
    __half* d = dst + (size_t)blockIdx.z*65536;
    int n0 = blockIdx.x*32, k0 = blockIdx.y*32;
    int tx = threadIdx.x, ty = threadIdx.y;
    #pragma unroll
    for (int j = 0; j < 4; j++)
        t[ty + j*8][tx] = src[(size_t)(k0 + ty + j*8)*256 + n0 + tx];
    __syncthreads();
    #pragma unroll
    for (int j = 0; j < 4; j++)
        d[(size_t)(n0 + ty + j*8)*256 + k0 + tx] = __float2half(t[tx][ty + j*8] * sc);
}

// ---------------- embedding + positional encoding ----------------
__global__ void k_embed(const int* __restrict__ tgt_in,
                        const float* __restrict__ emb,
                        __half* __restrict__ X,
                        float* __restrict__ out_ids, int write_ids)
{
    int r = blockIdx.x;
    int d = threadIdx.x;
    int b = r / TT, t = r % TT;
    int id = (t == 0) ? VOC : tgt_in[b*(TT-1) + (t-1)];
    if (d == 0) {
        g_padbuf[r] = (id != 0) ? 1.0f : 0.0f;
        if (write_ids) out_ids[r] = (t == 0) ? 0.0f : (float)id;
    }
    int i2 = d & ~1;
    float div = __expf(-(float)i2 * (9.210340371976184f / 256.0f));
    float ang = (float)t * div;
    float pe  = (d & 1) ? cosf(ang) : sinf(ang);
    X[(size_t)r*DD + d] = __float2half(2.0f*emb[(size_t)id*DD + d] + pe);
}

__global__ void k_encz(const int* __restrict__ src, const float* __restrict__ enc,
                       __half* __restrict__ E)
{
    int r = blockIdx.x;
    int d = threadIdx.x;
    E[(size_t)r*DD + d] = __float2half((src[r] != 0) ? enc[(size_t)r*DD + d] : 0.0f);
}

// ================= fp16 mma.sync GEMM (m16n8k16) ==========================
#define HTILE 10240
#define HSTAGE (2*HTILE)

__device__ __forceinline__ void hgemm_core(
    const __half* __restrict__ A, const __half* __restrict__ Bm,
    const float* __restrict__ bias, void* Cv,
    int M, int N, int K, int flags, char* sm)
{
    uint32_t sb = (uint32_t)__cvta_generic_to_shared(sm);
    int tid = threadIdx.x;
    int lane = tid & 31, warp = tid >> 5;
    int wm0 = (warp >> 2) * 64, wn0 = (warp & 3) * 32;
    int m0 = blockIdx.y * 128, n0 = blockIdx.x * 128;

    int r0 = tid >> 2, c0 = tid & 3;
    int r1 = (tid + 256) >> 2, c1 = tid & 3;

    const __half* srcA = A + (size_t)m0*K;
    const __half* srcB = Bm + (size_t)n0*K;

    uint32_t aBase = sb + (uint32_t)((wm0 + (lane & 15))*80 + (lane >> 4)*16);
    uint32_t bBase = sb + 10240u + (uint32_t)((wn0 + (lane & 15))*80 + (lane >> 4)*16);

    float acc[4][4][4];
    #pragma unroll
    for (int i = 0; i < 4; i++)
        #pragma unroll
        for (int j = 0; j < 4; j++) {
            acc[i][j][0]=0.f; acc[i][j][1]=0.f; acc[i][j][2]=0.f; acc[i][j][3]=0.f;
        }

    int nk = K >> 5;
    {
        uint32_t st = sb;
        cp16(st + (uint32_t)(r0*80 + c0*16),           srcA + (size_t)r0*K + c0*8);
        cp16(st + (uint32_t)(r1*80 + c1*16),           srcA + (size_t)r1*K + c1*8);
        cp16(st + 10240u + (uint32_t)(r0*80 + c0*16),  srcB + (size_t)r0*K + c0*8);
        cp16(st + 10240u + (uint32_t)(r1*80 + c1*16),  srcB + (size_t)r1*K + c1*8);
        asm volatile("cp.async.commit_group;");
        asm volatile("cp.async.wait_group 0;");
    }
    __syncthreads();

    for (int kt = 0; kt < nk; kt++) {
        int cur = kt & 1;
        if (kt + 1 < nk) {
            int k0 = (kt + 1) << 5;
            uint32_t st = sb + (uint32_t)(cur ^ 1)*HSTAGE;
            cp16(st + (uint32_t)(r0*80 + c0*16),          srcA + (size_t)r0*K + k0 + c0*8);
            cp16(st + (uint32_t)(r1*80 + c1*16),          srcA + (size_t)r1*K + k0 + c1*8);
            cp16(st + 10240u + (uint32_t)(r0*80 + c0*16), srcB + (size_t)r0*K + k0 + c0*8);
            cp16(st + 10240u + (uint32_t)(r1*80 + c1*16), srcB + (size_t)r1*K + k0 + c1*8);
            asm volatile("cp.async.commit_group;");
        }

        uint32_t aB = aBase + (uint32_t)cur*HSTAGE;
        uint32_t bB = bBase + (uint32_t)cur*HSTAGE;

        #pragma unroll
        for (int ks = 0; ks < 2; ks++) {
            uint32_t af[4][4], bf2[2][4];
            #pragma unroll
            for (int mt = 0; mt < 4; mt++) {
                uint32_t addr = aB + (uint32_t)(mt*16*80 + ks*32);
                asm volatile(
                    "ldmatrix.sync.aligned.m8n8.x4.shared.b16 {%0,%1,%2,%3}, [%4];"
                    : "=r"(af[mt][0]), "=r"(af[mt][1]), "=r"(af[mt][2]), "=r"(af[mt][3])
                    : "r"(addr));
            }
            #pragma unroll
            for (int nt16 = 0; nt16 < 2; nt16++) {
                uint32_t addr = bB + (uint32_t)(nt16*16*80 + ks*32);
                asm volatile(
                    "ldmatrix.sync.aligned.m8n8.x4.shared.b16 {%0,%1,%2,%3}, [%4];"
                    : "=r"(bf2[nt16][0]), "=r"(bf2[nt16][1]),
                      "=r"(bf2[nt16][2]), "=r"(bf2[nt16][3])
                    : "r"(addr));
            }
            #pragma unroll
            for (int mt = 0; mt < 4; mt++)
                #pragma unroll
                for (int nt = 0; nt < 4; nt++) {
                    uint32_t b0 = bf2[nt >> 1][nt & 1];
                    uint32_t b1 = bf2[nt >> 1][(nt & 1) + 2];
                    HMMA(acc[mt][nt], af[mt][0], af[mt][1], af[mt][2], af[mt][3], b0, b1);
                }
        }

        if (kt + 1 < nk) {
            asm volatile("cp.async.wait_group 0;");
            __syncthreads();
        }
    }

    int doGelu = flags & 1, outHalf = flags & 2;
    #pragma unroll
    for (int mt = 0; mt < 4; mt++) {
        int row0 = m0 + wm0 + mt*16 + (lane >> 2);
        #pragma unroll
        for (int nt = 0; nt < 4; nt++) {
            int col = n0 + wn0 + nt*8 + 2*(lane & 3);
            #pragma unroll
            for (int h = 0; h < 2; h++) {
                int rw = row0 + h*8;
                float v0 = acc[mt][nt][h*2+0];
                float v1 = acc[mt][nt][h*2+1];
                if (col + 1 < N) {
                    if (bias)  { v0 += bias[col]; v1 += bias[col+1]; }
                    if (doGelu){ v0 = gelu_f(v0); v1 = gelu_f(v1); }
                    if (outHalf) {
                        __half2 o; o.x = __float2half(v0); o.y = __float2half(v1);
                        *(__half2*)&((__half*)Cv)[(size_t)rw*N + col] = o;
                    } else {
                        float2 o; o.x = v0; o.y = v1;
                        *(float2*)&((float*)Cv)[(size_t)rw*N + col] = o;
                    }
                } else if (col < N) {
                    if (bias)  v0 += bias[col];
                    if (doGelu) v0 = gelu_f(v0);
                    if (outHalf) ((__half*)Cv)[(size_t)rw*N + col] = __float2half(v0);
                    else         ((float*)Cv)[(size_t)rw*N + col] = v0;
                }
            }
        }
    }
}

__global__ void __launch_bounds__(256)
k_hgemm(const __half* __restrict__ A, const __half* __restrict__ Bm,
        const float* __restrict__ bias, void* Cv, int M, int N, int K, int flags)
{
    __shared__ __align__(128) char sm[2*HSTAGE];
    hgemm_core(A, Bm, bias, Cv, M, N, K, flags, sm);
}

__global__ void __launch_bounds__(256)
k_hgemm3(const __half* a0, const __half* a1, const __half* a2,
         const __half* w0, const __half* w1, const __half* w2,
         __half* c0, __half* c1, __half* c2)
{
    __shared__ __align__(128) char sm[2*HSTAGE];
    const __half* A; const __half* W; __half* C;
    if (blockIdx.z == 0)      { A = a0; W = w0; C = c0; }
    else if (blockIdx.z == 1) { A = a1; W = w1; C = c1; }
    else                      { A = a2; W = w2; C = c2; }
    hgemm_core(A, W, nullptr, C, BT, DD, DD, 2, sm);   // fp16 out
}

// ================= FA2 tensor-core flash attention ========================
// 128 threads = 4 warps; warp handles 16 queries; CTA: 64 queries.
// Tiles of 64 keys; Q/K fp16 (scale folded into Wq), fp32 accum.
// Writes un-normalized partials (m, l, o) per NSPLIT; k_fmerge combines.
__global__ void __launch_bounds__(128)
k_fa2(const __half* __restrict__ Q, const __half* __restrict__ Kp,
      const __half* __restrict__ Vp, int lenK, int causal)
{
    __shared__ __align__(128) __half Qs[64*40];
    __shared__ __align__(128) __half KsS[2][64*40];
    __shared__ __align__(128) __half VsS[2][64*40];
    __shared__ float padsm[2][64];

    uint32_t sq  = (uint32_t)__cvta_generic_to_shared(Qs);
    uint32_t sk0 = (uint32_t)__cvta_generic_to_shared(KsS);
    uint32_t sv0 = (uint32_t)__cvta_generic_to_shared(VsS);

    int tid = threadIdx.x, lane = tid & 31, warp = tid >> 5;
    int bh = blockIdx.x, b = bh >> 3, h = bh & 7;
    int yb = blockIdx.y, z = blockIdx.z;
    int qbase = yb*64;

    int tilesTotal = lenK >> 6;
    int tps = tilesTotal / NSPLIT;
    int t0 = z*tps, t1 = t0 + tps;
    if (causal) { int need = yb + 1; if (t1 > need) t1 = need; }

    int r = lane >> 2, cq = lane & 3;
    int i0 = qbase + warp*16 + r;                   // local query idx (row r)
    size_t pb0 = (size_t)z*QH + (size_t)bh*TT + i0;
    size_t pb1 = pb0 + 8;

    if (t0 >= t1) {                                 // empty split
        if (cq == 0) {
            g_scratch[O_PM + pb0] = -CUDART_INF_F;  g_scratch[O_PL + pb0] = 0.f;
            g_scratch[O_PM + pb1] = -CUDART_INF_F;  g_scratch[O_PL + pb1] = 0.f;
        }
        #pragma unroll
        for (int nt = 0; nt < 4; nt++) {
            int c = nt*8 + cq*2;
            g_scratch[O_PO + pb0*32 + c]   = 0.f;
            g_scratch[O_PO + pb0*32 + c+1] = 0.f;
            g_scratch[O_PO + pb1*32 + c]   = 0.f;
            g_scratch[O_PO + pb1*32 + c+1] = 0.f;
        }
        return;
    }

    // load Q tile (64 x 32 halves)
    #pragma unroll
    for (int ii = 0; ii < 2; ii++) {
        int idx = tid + ii*128;
        int rr = idx >> 2, cc = idx & 3;
        cp16(sq + (uint32_t)(rr*80 + cc*16),
             Q + ((size_t)(b*TT + qbase + rr))*DD + h*32 + cc*8);
    }
    // load K/V tile t0 into stage 0
    {
        int j0 = t0*64;
        const __half* kb_ = Kp + ((size_t)b*lenK + j0)*DD + h*32;
        const __half* vb_ = Vp + ((size_t)b*lenK + j0)*DD + h*32;
        #pragma unroll
        for (int ii = 0; ii < 2; ii++) {
            int idx = tid + ii*128;
            int rr = idx >> 2, cc = idx & 3;
            cp16(sk0 + (uint32_t)(rr*80 + cc*16), kb_ + (size_t)rr*DD + cc*8);
            cp16(sv0 + (uint32_t)(rr*80 + cc*16), vb_ + (size_t)rr*DD + cc*8);
        }
        if (causal && tid < 64) padsm[0][tid] = g_padbuf[b*TT + j0 + tid];
    }
    asm volatile("cp.async.commit_group;");
    asm volatile("cp.async.wait_group 0;");
    __syncthreads();

    // Q fragments (held for the whole kernel)
    uint32_t aq[2][4];
    #pragma unroll
    for (int ks = 0; ks < 2; ks++) {
        uint32_t addr = sq + (uint32_t)((warp*16 + (lane & 15))*80 + ks*32 + (lane >> 4)*16);
        asm volatile(
            "ldmatrix.sync.aligned.m8n8.x4.shared.b16 {%0,%1,%2,%3}, [%4];"
            : "=r"(aq[ks][0]), "=r"(aq[ks][1]), "=r"(aq[ks][2]), "=r"(aq[ks][3])
            : "r"(addr));
    }

    const float NEG = -CUDART_INF_F;
    float m0 = NEG, m1 = NEG, l0 = 0.f, l1 = 0.f;
    float Oa[4][4];
    #pragma unroll
    for (int i = 0; i < 4; i++) { Oa[i][0]=0.f; Oa[i][1]=0.f; Oa[i][2]=0.f; Oa[i][3]=0.f; }

    for (int t = t0; t < t1; t++) {
        int st = (t - t0) & 1;
        int j0 = t*64;
        uint32_t skst = sk0 + (uint32_t)st*5120u;
        uint32_t svst = sv0 + (uint32_t)st*5120u;

        // S = Q @ K^T  (16x64 per warp)
        float S[8][4];
        #pragma unroll
        for (int i = 0; i < 8; i++) { S[i][0]=0.f; S[i][1]=0.f; S[i][2]=0.f; S[i][3]=0.f; }
        #pragma unroll
        for (int ks = 0; ks < 2; ks++) {
            uint32_t kb[4][4];
            #pragma unroll
            for (int g = 0; g < 4; g++) {
                uint32_t addr = skst + (uint32_t)((g*16 + (lane & 15))*80 + ks*32 + (lane >> 4)*16);
                asm volatile(
                    "ldmatrix.sync.aligned.m8n8.x4.shared.b16 {%0,%1,%2,%3}, [%4];"
                    : "=r"(kb[g][0]), "=r"(kb[g][1]), "=r"(kb[g][2]), "=r"(kb[g][3])
                    : "r"(addr));
            }
            #pragma unroll
            for (int g = 0; g < 4; g++) {
                HMMA(S[2*g],   aq[ks][0], aq[ks][1], aq[ks][2], aq[ks][3], kb[g][0], kb[g][2]);
                HMMA(S[2*g+1], aq[ks][0], aq[ks][1], aq[ks][2], aq[ks][3], kb[g][1], kb[g][3]);
            }
        }

        // prefetch next tile
        if (t + 1 < t1) {
            int jn = (t + 1)*64;
            uint32_t skn = sk0 + (uint32_t)(st ^ 1)*5120u;
            uint32_t svn = sv0 + (uint32_t)(st ^ 1)*5120u;
            const __half* kb_ = Kp + ((size_t)b*lenK + jn)*DD + h*32;
            const __half* vb_ = Vp + ((size_t)b*lenK + jn)*DD + h*32;
            #pragma unroll
            for (int ii = 0; ii < 2; ii++) {
                int idx = tid + ii*128;
                int rr = idx >> 2, cc = idx & 3;
                cp16(skn + (uint32_t)(rr*80 + cc*16), kb_ + (size_t)rr*DD + cc*8);
                cp16(svn + (uint32_t)(rr*80 + cc*16), vb_ + (size_t)rr*DD + cc*8);
            }
            if (causal && tid < 64) padsm[st ^ 1][tid] = g_padbuf[b*TT + jn + tid];
            asm volatile("cp.async.commit_group;");
        }

        // mask
        if (causal) {
            #pragma unroll
            for (int tn = 0; tn < 8; tn++) {
                int cb = tn*8 + cq*2;
                #pragma unroll
                for (int e = 0; e < 2; e++) {
                    int j = j0 + cb + e;
                    bool bad = (padsm[st][cb + e] == 0.0f);
                    if (j > i0     || bad) S[tn][e]     = NEG;
                    if (j > i0 + 8 || bad) S[tn][2 + e] = NEG;
                }
            }
        }

        // online softmax
        float mr0 = NEG, mr1 = NEG;
        #pragma unroll
        for (int tn = 0; tn < 8; tn++) {
            mr0 = fmaxf(mr0, fmaxf(S[tn][0], S[tn][1]));
            mr1 = fmaxf(mr1, fmaxf(S[tn][2], S[tn][3]));
        }
        mr0 = fmaxf(mr0, __shfl_xor_sync(0xFFFFFFFFu, mr0, 1));
        mr0 = fmaxf(mr0, __shfl_xor_sync(0xFFFFFFFFu, mr0, 2));
        mr1 = fmaxf(mr1, __shfl_xor_sync(0xFFFFFFFFu, mr1, 1));
        mr1 = fmaxf(mr1, __shfl_xor_sync(0xFFFFFFFFu, mr1, 2));

        float mn0 = fmaxf(m0, mr0), mn1 = fmaxf(m1, mr1);
        float ms0 = (mn0 == NEG) ? 0.f : mn0;
        float ms1 = (mn1 == NEG) ? 0.f : mn1;
        float c0 = __expf(m0 - ms0), c1 = __expf(m1 - ms1);

        float P[8][4];
        float s0 = 0.f, s1 = 0.f;
        #pragma unroll
        for (int tn = 0; tn < 8; tn++) {
            P[tn][0] = __expf(S[tn][0] - ms0);
            P[tn][1] = __expf(S[tn][1] - ms0);
            P[tn][2] = __expf(S[tn][2] - ms1);
            P[tn][3] = __expf(S[tn][3] - ms1);
            s0 += P[tn][0] + P[tn][1];
            s1 += P[tn][2] + P[tn][3];
        }
        s0 += __shfl_xor_sync(0xFFFFFFFFu, s0, 1);
        s0 += __shfl_xor_sync(0xFFFFFFFFu, s0, 2);
        s1 += __shfl_xor_sync(0xFFFFFFFFu, s1, 1);
        s1 += __shfl_xor_sync(0xFFFFFFFFu, s1, 2);
        l0 = l0*c0 + s0;
        l1 = l1*c1 + s1;
        m0 = mn0; m1 = mn1;

        #pragma unroll
        for (int nt = 0; nt < 4; nt++) {
            Oa[nt][0] *= c0; Oa[nt][1] *= c0;
            Oa[nt][2] *= c1; Oa[nt][3] *= c1;
        }

        // O += P @ V   (P fragments straight from registers; V via trans ldmatrix)
        #pragma unroll
        for (int ks2 = 0; ks2 < 4; ks2++) {
            uint32_t vb[2][4];
            #pragma unroll
            for (int ng = 0; ng < 2; ng++) {
                uint32_t addr = svst + (uint32_t)((ks2*16 + (lane & 15))*80 + ng*32 + (lane >> 4)*16);
                asm volatile(
                    "ldmatrix.sync.aligned.m8n8.x4.trans.shared.b16 {%0,%1,%2,%3}, [%4];"
                    : "=r"(vb[ng][0]), "=r"(vb[ng][1]), "=r"(vb[ng][2]), "=r"(vb[ng][3])
                    : "r"(addr));
            }
            uint32_t pa0 = packh2(P[2*ks2][0],   P[2*ks2][1]);
            uint32_t pa1 = packh2(P[2*ks2][2],   P[2*ks2][3]);
            uint32_t pa2 = packh2(P[2*ks2+1][0], P[2*ks2+1][1]);
            uint32_t pa3 = packh2(P[2*ks2+1][2], P[2*ks2+1][3]);
            HMMA(Oa[0], pa0, pa1, pa2, pa3, vb[0][0], vb[0][1]);
            HMMA(Oa[1], pa0, pa1, pa2, pa3, vb[0][2], vb[0][3]);
            HMMA(Oa[2], pa0, pa1, pa2, pa3, vb[1][0], vb[1][1]);
            HMMA(Oa[3], pa0, pa1, pa2, pa3, vb[1][2], vb[1][3]);
        }

        if (t + 1 < t1) {
            asm volatile("cp.async.wait_group 0;");
            __syncthreads();
        }
    }

    // write partials
    if (cq == 0) {
        g_scratch[O_PM + pb0] = m0;  g_scratch[O_PL + pb0] = l0;
        g_scratch[O_PM + pb1] = m1;  g_scratch[O_PL + pb1] = l1;
    }
    #pragma unroll
    for (int nt = 0; nt < 4; nt++) {
        int c = nt*8 + cq*2;
        g_scratch[O_PO + pb0*32 + c]   = Oa[nt][0];
        g_scratch[O_PO + pb0*32 + c+1] = Oa[nt][1];
        g_scratch[O_PO + pb1*32 + c]   = Oa[nt][2];
        g_scratch[O_PO + pb1*32 + c+1] = Oa[nt][3];
    }
}

__global__ void k_fmerge(__half* __restrict__ O)
{
    int idx = blockIdx.x*256 + threadIdx.x;
    int qh = idx >> 5, d = idx & 31;
    float M = -CUDART_INF_F;
    #pragma unroll
    for (int s = 0; s < NSPLIT; s++)
        M = fmaxf(M, g_scratch[O_PM + (size_t)s*QH + qh]);
    float L = 0.0f, acc = 0.0f;
    #pragma unroll
    for (int s = 0; s < NSPLIT; s++) {
        size_t base = (size_t)s*QH + qh;
        float w = __expf(g_scratch[O_PM + base] - M);
        L   += w * g_scratch[O_PL + base];
        acc += w * g_scratch[O_PO + base*32 + d];
    }
    int bh = qh / TT, i = qh % TT;
    int b = bh / HH, h = bh % HH;
    O[(size_t)(b*TT + i)*DD + h*32 + d] = __float2half(acc / L);
}

// ---------------- fused residual-add + LayerNorm -------------------------
__global__ void k_addln(const __half* __restrict__ X, const float* __restrict__ A,
                        const float* __restrict__ g, const float* __restrict__ be,
                        __half* __restrict__ Y)
{
    int r = blockIdx.x, d = threadIdx.x;
    float v = __half2float(X[(size_t)r*DD + d]) + A[(size_t)r*DD + d];
    __shared__ float sh[18];
    float s1 = v, s2 = v*v;
    #pragma unroll
    for (int off = 16; off; off >>= 1) {
        s1 += __shfl_down_sync(0xFFFFFFFFu, s1, off);
        s2 += __shfl_down_sync(0xFFFFFFFFu, s2, off);
    }
    int warp = d >> 5, lane = d & 31;
    if (lane == 0) { sh[warp] = s1; sh[8 + warp] = s2; }
    __syncthreads();
    if (d == 0) {
        float t1 = 0.f, t2 = 0.f;
        for (int w = 0; w < 8; w++) { t1 += sh[w]; t2 += sh[8 + w]; }
        float mean = t1 * (1.0f/256.0f);
        float var  = t2 * (1.0f/256.0f) - mean*mean;
        sh[16] = mean;
        sh[17] = rsqrtf(var + 1e-5f);
    }
    __syncthreads();
    Y[(size_t)r*DD + d] = __float2half((v - sh[16])*sh[17]*g[d] + be[d]);
}

// ---------------- host orchestration -------------------------------------
extern "C" void kernel_launch(void* const* d_in, const int* in_sizes, int n_in,
                              void* d_out, int out_size)
{
    const int*   src   = (const int*)  d_in[0];
    const int*   tgt   = (const int*)  d_in[1];
    const float* enc   = (const float*)d_in[2];
    const float* emb   = (const float*)d_in[3];
    const float* Wq_s  = (const float*)d_in[4];
    const float* Wk_s  = (const float*)d_in[5];
    const float* Wv_s  = (const float*)d_in[6];
    const float* Wo_s  = (const float*)d_in[7];
    const float* bo_s  = (const float*)d_in[8];
    const float* Wq_c  = (const float*)d_in[9];
    const float* Wk_c  = (const float*)d_in[10];
    const float* Wv_c  = (const float*)d_in[11];
    const float* Wo_c  = (const float*)d_in[12];
    const float* bo_c  = (const float*)d_in[13];
    const float* W1    = (const float*)d_in[14];
    const float* b1    = (const float*)d_in[15];
    const float* W2    = (const float*)d_in[16];
    const float* b2    = (const float*)d_in[17];
    const float* g1    = (const float*)d_in[18];
    const float* be1   = (const float*)d_in[19];
    const float* g2    = (const float*)d_in[20];
    const float* be2   = (const float*)d_in[21];
    const float* g3    = (const float*)d_in[22];
    const float* be3   = (const float*)d_in[23];
    const float* Wf    = (const float*)d_in[24];
    const float* bf    = (const float*)d_in[25];
    float* out = (float*)d_out;

    float* s = nullptr;
    cudaGetSymbolAddress((void**)&s, g_scratch);
    __half* x0h  = (__half*)(s + O_X0);
    __half* x1h  = (__half*)(s + O_X1);
    __half* x2h  = (__half*)(s + O_X2);
    __half* x3h  = (__half*)(s + O_X3);
    __half* qh_  = (__half*)(s + O_Q);
    __half* kh_  = (__half*)(s + O_K);
    __half* vh_  = (__half*)(s + O_V);
    __half* atth = (__half*)(s + O_ATT);
    float*  proj = s + O_PROJ;
    __half* ench = (__half*)(s + O_ENCZ);
    __half* ffh  = (__half*)(s + O_FF);
    __half* whA  = (__half*)(s + O_WH);
    __half* w1h  = (__half*)(s + O_W1H);
    __half* w2h  = (__half*)(s + O_W2H);
    __half* wfh  = (__half*)(s + O_WFH);

    __half* wqs = whA + 0*65536;
    __half* wks = whA + 1*65536;
    __half* wvs = whA + 2*65536;
    __half* wos = whA + 3*65536;
    __half* wqc = whA + 4*65536;
    __half* wkc = whA + 5*65536;
    __half* wvc = whA + 6*65536;
    __half* woc = whA + 7*65536;

    long long logitsN = (long long)BT * VOC;
    int write_ids = ((long long)out_size >= logitsN + BT);
    float* out_ids = out + logitsN;

    dim3 t32x8(32, 8);

    // ---- weight prep + embeddings ----
    k_transpW8<<<dim3(8, 8, 8), t32x8>>>(Wq_s, Wk_s, Wv_s, Wo_s, Wq_c, Wk_c, Wv_c, Wo_c, whA);
    k_transp<<<dim3(FFD/32, DD/32),  t32x8>>>(W1, w1h, DD, FFD);
    k_transp<<<dim3(DD/32,  FFD/32), t32x8>>>(W2, w2h, FFD, DD);
    k_transp<<<dim3(VOCP/32, DD/32), t32x8>>>(Wf, wfh, DD, VOC);
    k_embed<<<BT, 256>>>(tgt, emb, x0h, out_ids, write_ids);
    k_encz <<<BB*SS, 256>>>(src, enc, ench);

    // ---- self attention ----
    k_hgemm3<<<dim3(2, 32, 3), 256>>>(x0h, x0h, x0h, wqs, wks, wvs, qh_, kh_, vh_);
    k_fa2<<<dim3(BB*HH, TT/64, NSPLIT), 128>>>(qh_, kh_, vh_, TT, 1);
    k_fmerge<<<QH*32/256, 256>>>(atth);
    k_hgemm<<<dim3(2, 32), 256>>>(atth, wos, bo_s, proj, BT, DD, DD, 0);
    k_addln<<<BT, 256>>>(x0h, proj, g1, be1, x1h);

    // ---- cross attention ----
    k_hgemm3<<<dim3(2, 32, 3), 256>>>(x1h, ench, ench, wqc, wkc, wvc, qh_, kh_, vh_);
    k_fa2<<<dim3(BB*HH, TT/64, NSPLIT), 128>>>(qh_, kh_, vh_, SS, 0);
    k_fmerge<<<QH*32/256, 256>>>(atth);
    k_hgemm<<<dim3(2, 32), 256>>>(atth, woc, bo_c, proj, BT, DD, DD, 0);
    k_addln<<<BT, 256>>>(x1h, proj, g2, be2, x2h);

    // ---- feed forward ----
    k_hgemm<<<dim3(16, 32), 256>>>(x2h, w1h, b1, ffh, BT, FFD, DD, 3);
    k_hgemm<<<dim3(2, 32),  256>>>(ffh, w2h, b2, proj, BT, DD, FFD, 0);
    k_addln<<<BT, 256>>>(x2h, proj, g3, be3, x3h);

    // ---- vocab projection into d_out ----
    k_hgemm<<<dim3(VOCP/128, 32), 256>>>(x3h, wfh, bf, out, BT, VOC, DD, 0);
}

// round 16
// speedup vs baseline: 2.5935x; 1.0357x over previous
#include <cuda_runtime.h>
#include <cuda_fp16.h>
#include <math.h>
#include <math_constants.h>
#include <stdint.h>

#define BB 2
#define TT 2048
#define SS 2048
#define DD 256
#define HH 8
#define FFD 2048
#define VOC 25426
#define VOCP 25472              // padded vocab (199*128)
#define BT (BB*TT)
#define QH (BB*HH*TT)
#define NSPLIT 4

// ---------------- scratch ----------------
#define SLAB 1048576
#define O_X0   (0*SLAB)
#define O_X1   (1*SLAB)
#define O_X2   (2*SLAB)
#define O_X3   (3*SLAB)
#define O_Q    (4*SLAB)
#define O_K    (5*SLAB)
#define O_V    (6*SLAB)
#define O_ATT  (7*SLAB)
#define O_PROJ (8*SLAB)
#define O_ENCZ (9*SLAB)
#define O_FF   ((size_t)10*SLAB)                 // ff halves: 4 slabs (10..13)
#define O_KC   ((size_t)14*SLAB)                 // cross K halves
#define O_VC   ((size_t)15*SLAB)                 // cross V halves
#define O_PO   ((size_t)18*SLAB)                 // NSPLIT*QH*32 = 4 slabs
#define O_PM   ((size_t)26*SLAB)
#define O_PL   ((size_t)26*SLAB + NSPLIT*QH)
#define O_WH   ((size_t)27*SLAB)                 // 8 att weights fp16 [256][256]
#define O_W1H  (O_WH  + 8*32768)
#define O_W2H  (O_W1H + 262144)
#define O_WFH  (O_W2H + 262144)                  // [VOCP][256] fp16
#define SCRATCH_FLOATS ((size_t)35*SLAB)

__device__ float g_scratch[SCRATCH_FLOATS];
__device__ float g_padbuf[BT];

__device__ __forceinline__ float gelu_f(float v) {
    return 0.5f*v*(1.0f + erff(v*0.70710678118654752f));
}
__device__ __forceinline__ void cp16(uint32_t dst, const void* src) {
    asm volatile("cp.async.cg.shared.global [%0], [%1], 16;" :: "r"(dst), "l"(src));
}
#define HMMA(acc, a0, a1, a2, a3, b0, b1) \
    asm volatile( \
        "mma.sync.aligned.m16n8k16.row.col.f32.f16.f16.f32 " \
        "{%0,%1,%2,%3}, {%4,%5,%6,%7}, {%8,%9}, {%0,%1,%2,%3};" \
        : "+f"((acc)[0]), "+f"((acc)[1]), "+f"((acc)[2]), "+f"((acc)[3]) \
        : "r"(a0), "r"(a1), "r"(a2), "r"(a3), "r"(b0), "r"(b1))

__device__ __forceinline__ uint32_t packh2(float lo, float hi) {
    uint32_t u;
    asm("cvt.rn.f16x2.f32 %0, %1, %2;" : "=r"(u) : "f"(hi), "f"(lo));
    return u;
}

// ---------------- fused embedding/PE + encoder-zero ----------------
__global__ void k_embedencz(const int* __restrict__ tgt_in, const float* __restrict__ emb,
                            __half* __restrict__ X,
                            const int* __restrict__ src, const float* __restrict__ enc,
                            __half* __restrict__ E,
                            float* __restrict__ out_ids, int write_ids)
{
    int r = blockIdx.x;
    int d = threadIdx.x;
    if (r < BT) {
        int b = r / TT, t = r % TT;
        int id = (t == 0) ? VOC : tgt_in[b*(TT-1) + (t-1)];
        if (d == 0) {
            g_padbuf[r] = (id != 0) ? 1.0f : 0.0f;
            if (write_ids) out_ids[r] = (t == 0) ? 0.0f : (float)id;
        }
        int i2 = d & ~1;
        float div = __expf(-(float)i2 * (9.210340371976184f / 256.0f));
        float ang = (float)t * div;
        float pe  = (d & 1) ? cosf(ang) : sinf(ang);
        X[(size_t)r*DD + d] = __float2half(2.0f*emb[(size_t)id*DD + d] + pe);
    } else {
        int rr = r - BT;
        E[(size_t)rr*DD + d] = __float2half((src[rr] != 0) ? enc[(size_t)rr*DD + d] : 0.0f);
    }
}

// ---------------- weight prep: fp32 [K][N] -> fp16 [Npad][K] -----------
__global__ void k_transp(const float* __restrict__ src, __half* __restrict__ dst,
                         int K, int N)
{
    __shared__ float t[32][33];
    int n0 = blockIdx.x*32, k0 = blockIdx.y*32;
    int tx = threadIdx.x, ty = threadIdx.y;
    #pragma unroll
    for (int j = 0; j < 4; j++) {
        int k = k0 + ty + j*8, n = n0 + tx;
        t[ty + j*8][tx] = (n < N) ? src[(size_t)k*N + n] : 0.0f;
    }
    __syncthreads();
    #pragma unroll
    for (int j = 0; j < 4; j++) {
        int n = n0 + ty + j*8, k = k0 + tx;
        dst[(size_t)n*K + k] = __float2half(t[tx][ty + j*8]);
    }
}

// att weights; Wq_s (idx 0) and Wq_c (idx 4) pre-scaled by log2(e)/sqrt(32)
__global__ void k_transpW8(const float* w0, const float* w1, const float* w2, const float* w3,
                           const float* w4, const float* w5, const float* w6, const float* w7,
                           __half* __restrict__ dst)
{
    __shared__ float t[32][33];
    const float* src;
    switch (blockIdx.z) {
        case 0: src = w0; break; case 1: src = w1; break;
        case 2: src = w2; break; case 3: src = w3; break;
        case 4: src = w4; break; case 5: src = w5; break;
        case 6: src = w6; break; default: src = w7; break;
    }
    float sc = (blockIdx.z == 0 || blockIdx.z == 4)
             ? (0.17677669529663687f * 1.4426950408889634f) : 1.0f;
    __half* d = dst + (size_t)blockIdx.z*65536;
    int n0 = blockIdx.x*32, k0 = blockIdx.y*32;
    int tx = threadIdx.x, ty = threadIdx.y;
    #pragma unroll
    for (int j = 0; j < 4; j++)
        t[ty + j*8][tx] = src[(size_t)(k0 + ty + j*8)*256 + n0 + tx];
    __syncthreads();
    #pragma unroll
    for (int j = 0; j < 4; j++)
        d[(size_t)(n0 + ty + j*8)*256 + k0 + tx] = __float2half(t[tx][ty + j*8] * sc);
}

// ================= fp16 mma.sync GEMM, 128x128 tile =======================
#define HTILE 10240
#define HSTAGE (2*HTILE)

__device__ __forceinline__ void hgemm_core(
    const __half* __restrict__ A, const __half* __restrict__ Bm,
    const float* __restrict__ bias, void* Cv,
    int M, int N, int K, int flags, char* sm)
{
    uint32_t sb = (uint32_t)__cvta_generic_to_shared(sm);
    int tid = threadIdx.x;
    int lane = tid & 31, warp = tid >> 5;
    int wm0 = (warp >> 2) * 64, wn0 = (warp & 3) * 32;
    int m0 = blockIdx.y * 128, n0 = blockIdx.x * 128;

    int r0 = tid >> 2, c0 = tid & 3;
    int r1 = (tid + 256) >> 2, c1 = tid & 3;

    const __half* srcA = A + (size_t)m0*K;
    const __half* srcB = Bm + (size_t)n0*K;

    uint32_t aBase = sb + (uint32_t)((wm0 + (lane & 15))*80 + (lane >> 4)*16);
    uint32_t bBase = sb + 10240u + (uint32_t)((wn0 + (lane & 15))*80 + (lane >> 4)*16);

    float acc[4][4][4];
    #pragma unroll
    for (int i = 0; i < 4; i++)
        #pragma unroll
        for (int j = 0; j < 4; j++) {
            acc[i][j][0]=0.f; acc[i][j][1]=0.f; acc[i][j][2]=0.f; acc[i][j][3]=0.f;
        }

    int nk = K >> 5;
    {
        uint32_t st = sb;
        cp16(st + (uint32_t)(r0*80 + c0*16),           srcA + (size_t)r0*K + c0*8);
        cp16(st + (uint32_t)(r1*80 + c1*16),           srcA + (size_t)r1*K + c1*8);
        cp16(st + 10240u + (uint32_t)(r0*80 + c0*16),  srcB + (size_t)r0*K + c0*8);
        cp16(st + 10240u + (uint32_t)(r1*80 + c1*16),  srcB + (size_t)r1*K + c1*8);
        asm volatile("cp.async.commit_group;");
        asm volatile("cp.async.wait_group 0;");
    }
    __syncthreads();

    for (int kt = 0; kt < nk; kt++) {
        int cur = kt & 1;
        if (kt + 1 < nk) {
            int k0 = (kt + 1) << 5;
            uint32_t st = sb + (uint32_t)(cur ^ 1)*HSTAGE;
            cp16(st + (uint32_t)(r0*80 + c0*16),          srcA + (size_t)r0*K + k0 + c0*8);
            cp16(st + (uint32_t)(r1*80 + c1*16),          srcA + (size_t)r1*K + k0 + c1*8);
            cp16(st + 10240u + (uint32_t)(r0*80 + c0*16), srcB + (size_t)r0*K + k0 + c0*8);
            cp16(st + 10240u + (uint32_t)(r1*80 + c1*16), srcB + (size_t)r1*K + k0 + c1*8);
            asm volatile("cp.async.commit_group;");
        }

        uint32_t aB = aBase + (uint32_t)cur*HSTAGE;
        uint32_t bB = bBase + (uint32_t)cur*HSTAGE;

        #pragma unroll
        for (int ks = 0; ks < 2; ks++) {
            uint32_t af[4][4], bf2[2][4];
            #pragma unroll
            for (int mt = 0; mt < 4; mt++) {
                uint32_t addr = aB + (uint32_t)(mt*16*80 + ks*32);
                asm volatile(
                    "ldmatrix.sync.aligned.m8n8.x4.shared.b16 {%0,%1,%2,%3}, [%4];"
                    : "=r"(af[mt][0]), "=r"(af[mt][1]), "=r"(af[mt][2]), "=r"(af[mt][3])
                    : "r"(addr));
            }
            #pragma unroll
            for (int nt16 = 0; nt16 < 2; nt16++) {
                uint32_t addr = bB + (uint32_t)(nt16*16*80 + ks*32);
                asm volatile(
                    "ldmatrix.sync.aligned.m8n8.x4.shared.b16 {%0,%1,%2,%3}, [%4];"
                    : "=r"(bf2[nt16][0]), "=r"(bf2[nt16][1]),
                      "=r"(bf2[nt16][2]), "=r"(bf2[nt16][3])
                    : "r"(addr));
            }
            #pragma unroll
            for (int mt = 0; mt < 4; mt++)
                #pragma unroll
                for (int nt = 0; nt < 4; nt++) {
                    uint32_t b0 = bf2[nt >> 1][nt & 1];
                    uint32_t b1 = bf2[nt >> 1][(nt & 1) + 2];
                    HMMA(acc[mt][nt], af[mt][0], af[mt][1], af[mt][2], af[mt][3], b0, b1);
                }
        }

        if (kt + 1 < nk) {
            asm volatile("cp.async.wait_group 0;");
            __syncthreads();
        }
    }

    int doGelu = flags & 1, outHalf = flags & 2;
    #pragma unroll
    for (int mt = 0; mt < 4; mt++) {
        int row0 = m0 + wm0 + mt*16 + (lane >> 2);
        #pragma unroll
        for (int nt = 0; nt < 4; nt++) {
            int col = n0 + wn0 + nt*8 + 2*(lane & 3);
            #pragma unroll
            for (int h = 0; h < 2; h++) {
                int rw = row0 + h*8;
                float v0 = acc[mt][nt][h*2+0];
                float v1 = acc[mt][nt][h*2+1];
                if (col + 1 < N) {
                    if (bias)  { v0 += bias[col]; v1 += bias[col+1]; }
                    if (doGelu){ v0 = gelu_f(v0); v1 = gelu_f(v1); }
                    if (outHalf) {
                        __half2 o; o.x = __float2half(v0); o.y = __float2half(v1);
                        *(__half2*)&((__half*)Cv)[(size_t)rw*N + col] = o;
                    } else {
                        float2 o; o.x = v0; o.y = v1;
                        *(float2*)&((float*)Cv)[(size_t)rw*N + col] = o;
                    }
                } else if (col < N) {
                    if (bias)  v0 += bias[col];
                    if (doGelu) v0 = gelu_f(v0);
                    if (outHalf) ((__half*)Cv)[(size_t)rw*N + col] = __float2half(v0);
                    else         ((float*)Cv)[(size_t)rw*N + col] = v0;
                }
            }
        }
    }
}

__global__ void __launch_bounds__(256)
k_hgemm(const __half* __restrict__ A, const __half* __restrict__ Bm,
        const float* __restrict__ bias, void* Cv, int M, int N, int K, int flags)
{
    __shared__ __align__(128) char sm[2*HSTAGE];
    hgemm_core(A, Bm, bias, Cv, M, N, K, flags, sm);
}

// ================= fp16 mma.sync GEMM, 64x128 tile ========================
// 8 warps as 2m x 4n, warp tile 32x32. smem stage: A 64x80B + B 128x80B.
#define H64A 5120
#define H64STAGE 15360

__device__ __forceinline__ void hgemm64_core(
    const __half* __restrict__ A, const __half* __restrict__ Bm,
    const float* __restrict__ bias, void* Cv,
    int N, int K, int flags, char* sm)
{
    uint32_t sb = (uint32_t)__cvta_generic_to_shared(sm);
    int tid = threadIdx.x;
    int lane = tid & 31, warp = tid >> 5;
    int wm0 = (warp >> 2) * 32, wn0 = (warp & 3) * 32;
    int m0 = blockIdx.y * 64, n0 = blockIdx.x * 128;

    int ra = tid >> 2, ca = tid & 3;                 // A: 256 chunks, 1/thread
    int rb0 = tid >> 2, rb1 = (tid + 256) >> 2;      // B: 512 chunks, 2/thread

    const __half* srcA = A + (size_t)m0*K;
    const __half* srcB = Bm + (size_t)n0*K;

    uint32_t aBase = sb + (uint32_t)((wm0 + (lane & 15))*80 + (lane >> 4)*16);
    uint32_t bBase = sb + (uint32_t)H64A + (uint32_t)((wn0 + (lane & 15))*80 + (lane >> 4)*16);

    float acc[2][4][4];
    #pragma unroll
    for (int i = 0; i < 2; i++)
        #pragma unroll
        for (int j = 0; j < 4; j++) {
            acc[i][j][0]=0.f; acc[i][j][1]=0.f; acc[i][j][2]=0.f; acc[i][j][3]=0.f;
        }

    int nk = K >> 5;
    {
        uint32_t st = sb;
        cp16(st + (uint32_t)(ra*80 + ca*16),                 srcA + (size_t)ra*K + ca*8);
        cp16(st + H64A + (uint32_t)(rb0*80 + ca*16),         srcB + (size_t)rb0*K + ca*8);
        cp16(st + H64A + (uint32_t)(rb1*80 + ca*16),         srcB + (size_t)rb1*K + ca*8);
        asm volatile("cp.async.commit_group;");
        asm volatile("cp.async.wait_group 0;");
    }
    __syncthreads();

    for (int kt = 0; kt < nk; kt++) {
        int cur = kt & 1;
        if (kt + 1 < nk) {
            int k0 = (kt + 1) << 5;
            uint32_t st = sb + (uint32_t)(cur ^ 1)*H64STAGE;
            cp16(st + (uint32_t)(ra*80 + ca*16),          srcA + (size_t)ra*K + k0 + ca*8);
            cp16(st + H64A + (uint32_t)(rb0*80 + ca*16),  srcB + (size_t)rb0*K + k0 + ca*8);
            cp16(st + H64A + (uint32_t)(rb1*80 + ca*16),  srcB + (size_t)rb1*K + k0 + ca*8);
            asm volatile("cp.async.commit_group;");
        }

        uint32_t aB = aBase + (uint32_t)cur*H64STAGE;
        uint32_t bB = bBase + (uint32_t)cur*H64STAGE;

        #pragma unroll
        for (int ks = 0; ks < 2; ks++) {
            uint32_t af[2][4], bf2[2][4];
            #pragma unroll
            for (int mt = 0; mt < 2; mt++) {
                uint32_t addr = aB + (uint32_t)(mt*16*80 + ks*32);
                asm volatile(
                    "ldmatrix.sync.aligned.m8n8.x4.shared.b16 {%0,%1,%2,%3}, [%4];"
                    : "=r"(af[mt][0]), "=r"(af[mt][1]), "=r"(af[mt][2]), "=r"(af[mt][3])
                    : "r"(addr));
            }
            #pragma unroll
            for (int nt16 = 0; nt16 < 2; nt16++) {
                uint32_t addr = bB + (uint32_t)(nt16*16*80 + ks*32);
                asm volatile(
                    "ldmatrix.sync.aligned.m8n8.x4.shared.b16 {%0,%1,%2,%3}, [%4];"
                    : "=r"(bf2[nt16][0]), "=r"(bf2[nt16][1]),
                      "=r"(bf2[nt16][2]), "=r"(bf2[nt16][3])
                    : "r"(addr));
            }
            #pragma unroll
            for (int mt = 0; mt < 2; mt++)
                #pragma unroll
                for (int nt = 0; nt < 4; nt++) {
                    uint32_t b0 = bf2[nt >> 1][nt & 1];
                    uint32_t b1 = bf2[nt >> 1][(nt & 1) + 2];
                    HMMA(acc[mt][nt], af[mt][0], af[mt][1], af[mt][2], af[mt][3], b0, b1);
                }
        }

        if (kt + 1 < nk) {
            asm volatile("cp.async.wait_group 0;");
            __syncthreads();
        }
    }

    int doGelu = flags & 1, outHalf = flags & 2;
    #pragma unroll
    for (int mt = 0; mt < 2; mt++) {
        int row0 = m0 + wm0 + mt*16 + (lane >> 2);
        #pragma unroll
        for (int nt = 0; nt < 4; nt++) {
            int col = n0 + wn0 + nt*8 + 2*(lane & 3);
            #pragma unroll
            for (int h = 0; h < 2; h++) {
                int rw = row0 + h*8;
                float v0 = acc[mt][nt][h*2+0];
                float v1 = acc[mt][nt][h*2+1];
                if (col + 1 < N) {
                    if (bias)  { v0 += bias[col]; v1 += bias[col+1]; }
                    if (doGelu){ v0 = gelu_f(v0); v1 = gelu_f(v1); }
                    if (outHalf) {
                        __half2 o; o.x = __float2half(v0); o.y = __float2half(v1);
                        *(__half2*)&((__half*)Cv)[(size_t)rw*N + col] = o;
                    } else {
                        float2 o; o.x = v0; o.y = v1;
                        *(float2*)&((float*)Cv)[(size_t)rw*N + col] = o;
                    }
                }
            }
        }
    }
}

__global__ void __launch_bounds__(256)
k_hgemm64(const __half* __restrict__ A, const __half* __restrict__ Bm,
          const float* __restrict__ bias, void* Cv, int N, int K, int flags)
{
    __shared__ __align__(128) char sm[2*H64STAGE];
    hgemm64_core(A, Bm, bias, Cv, N, K, flags, sm);
}

// fused 5-way: self Q,K,V + cross K,V. grid (2, 64, 5).
__global__ void __launch_bounds__(256)
k_hgemm5(const __half* xs, const __half* ec,
         const __half* w0, const __half* w1, const __half* w2,
         const __half* w3, const __half* w4,
         __half* c0, __half* c1, __half* c2, __half* c3, __half* c4)
{
    __shared__ __align__(128) char sm[2*H64STAGE];
    const __half* A; const __half* W; __half* C;
    switch (blockIdx.z) {
        case 0: A = xs; W = w0; C = c0; break;
        case 1: A = xs; W = w1; C = c1; break;
        case 2: A = xs; W = w2; C = c2; break;
        case 3: A = ec; W = w3; C = c3; break;
        default:A = ec; W = w4; C = c4; break;
    }
    hgemm64_core(A, W, nullptr, C, DD, DD, 2, sm);
}

// ================= FA2 tensor-core flash attention (exp2 domain) ==========
__global__ void __launch_bounds__(128)
k_fa2(const __half* __restrict__ Q, const __half* __restrict__ Kp,
      const __half* __restrict__ Vp, int lenK, int causal)
{
    __shared__ __align__(128) __half Qs[64*40];
    __shared__ __align__(128) __half KsS[2][64*40];
    __shared__ __align__(128) __half VsS[2][64*40];
    __shared__ float padsm[2][64];

    uint32_t sq  = (uint32_t)__cvta_generic_to_shared(Qs);
    uint32_t sk0 = (uint32_t)__cvta_generic_to_shared(KsS);
    uint32_t sv0 = (uint32_t)__cvta_generic_to_shared(VsS);

    int tid = threadIdx.x, lane = tid & 31, warp = tid >> 5;
    int bh = blockIdx.x, b = bh >> 3, h = bh & 7;
    int yb = blockIdx.y, z = blockIdx.z;
    int qbase = yb*64;

    int tilesTotal = lenK >> 6;
    int tps = tilesTotal / NSPLIT;
    int t0 = z*tps, t1 = t0 + tps;
    if (causal) { int need = yb + 1; if (t1 > need) t1 = need; }

    int r = lane >> 2, cq = lane & 3;
    int i0 = qbase + warp*16 + r;
    size_t pb0 = (size_t)z*QH + (size_t)bh*TT + i0;
    size_t pb1 = pb0 + 8;

    if (t0 >= t1) {
        if (cq == 0) {
            g_scratch[O_PM + pb0] = -CUDART_INF_F;  g_scratch[O_PL + pb0] = 0.f;
            g_scratch[O_PM + pb1] = -CUDART_INF_F;  g_scratch[O_PL + pb1] = 0.f;
        }
        #pragma unroll
        for (int nt = 0; nt < 4; nt++) {
            int c = nt*8 + cq*2;
            g_scratch[O_PO + pb0*32 + c]   = 0.f;
            g_scratch[O_PO + pb0*32 + c+1] = 0.f;
            g_scratch[O_PO + pb1*32 + c]   = 0.f;
            g_scratch[O_PO + pb1*32 + c+1] = 0.f;
        }
        return;
    }

    #pragma unroll
    for (int ii = 0; ii < 2; ii++) {
        int idx = tid + ii*128;
        int rr = idx >> 2, cc = idx & 3;
        cp16(sq + (uint32_t)(rr*80 + cc*16),
             Q + ((size_t)(b*TT + qbase + rr))*DD + h*32 + cc*8);
    }
    {
        int j0 = t0*64;
        const __half* kb_ = Kp + ((size_t)b*lenK + j0)*DD + h*32;
        const __half* vb_ = Vp + ((size_t)b*lenK + j0)*DD + h*32;
        #pragma unroll
        for (int ii = 0; ii < 2; ii++) {
            int idx = tid + ii*128;
            int rr = idx >> 2, cc = idx & 3;
            cp16(sk0 + (uint32_t)(rr*80 + cc*16), kb_ + (size_t)rr*DD + cc*8);
            cp16(sv0 + (uint32_t)(rr*80 + cc*16), vb_ + (size_t)rr*DD + cc*8);
        }
        if (causal && tid < 64) padsm[0][tid] = g_padbuf[b*TT + j0 + tid];
    }
    asm volatile("cp.async.commit_group;");
    asm volatile("cp.async.wait_group 0;");
    __syncthreads();

    uint32_t aq[2][4];
    #pragma unroll
    for (int ks = 0; ks < 2; ks++) {
        uint32_t addr = sq + (uint32_t)((warp*16 + (lane & 15))*80 + ks*32 + (lane >> 4)*16);
        asm volatile(
            "ldmatrix.sync.aligned.m8n8.x4.shared.b16 {%0,%1,%2,%3}, [%4];"
            : "=r"(aq[ks][0]), "=r"(aq[ks][1]), "=r"(aq[ks][2]), "=r"(aq[ks][3])
            : "r"(addr));
    }

    const float NEG = -CUDART_INF_F;
    float m0 = NEG, m1 = NEG, l0 = 0.f, l1 = 0.f;
    float Oa[4][4];
    #pragma unroll
    for (int i = 0; i < 4; i++) { Oa[i][0]=0.f; Oa[i][1]=0.f; Oa[i][2]=0.f; Oa[i][3]=0.f; }

    for (int t = t0; t < t1; t++) {
        int st = (t - t0) & 1;
        int j0 = t*64;
        uint32_t skst = sk0 + (uint32_t)st*5120u;
        uint32_t svst = sv0 + (uint32_t)st*5120u;

        float S[8][4];
        #pragma unroll
        for (int i = 0; i < 8; i++) { S[i][0]=0.f; S[i][1]=0.f; S[i][2]=0.f; S[i][3]=0.f; }
        #pragma unroll
        for (int ks = 0; ks < 2; ks++) {
            uint32_t kb[4][4];
            #pragma unroll
            for (int g = 0; g < 4; g++) {
                uint32_t addr = skst + (uint32_t)((g*16 + (lane & 15))*80 + ks*32 + (lane >> 4)*16);
                asm volatile(
                    "ldmatrix.sync.aligned.m8n8.x4.shared.b16 {%0,%1,%2,%3}, [%4];"
                    : "=r"(kb[g][0]), "=r"(kb[g][1]), "=r"(kb[g][2]), "=r"(kb[g][3])
                    : "r"(addr));
            }
            #pragma unroll
            for (int g = 0; g < 4; g++) {
                HMMA(S[2*g],   aq[ks][0], aq[ks][1], aq[ks][2], aq[ks][3], kb[g][0], kb[g][2]);
                HMMA(S[2*g+1], aq[ks][0], aq[ks][1], aq[ks][2], aq[ks][3], kb[g][1], kb[g][3]);
            }
        }

        if (t + 1 < t1) {
            int jn = (t + 1)*64;
            uint32_t skn = sk0 + (uint32_t)(st ^ 1)*5120u;
            uint32_t svn = sv0 + (uint32_t)(st ^ 1)*5120u;
            const __half* kb_ = Kp + ((size_t)b*lenK + jn)*DD + h*32;
            const __half* vb_ = Vp + ((size_t)b*lenK + jn)*DD + h*32;
            #pragma unroll
            for (int ii = 0; ii < 2; ii++) {
                int idx = tid + ii*128;
                int rr = idx >> 2, cc = idx & 3;
                cp16(skn + (uint32_t)(rr*80 + cc*16), kb_ + (size_t)rr*DD + cc*8);
                cp16(svn + (uint32_t)(rr*80 + cc*16), vb_ + (size_t)rr*DD + cc*8);
            }
            if (causal && tid < 64) padsm[st ^ 1][tid] = g_padbuf[b*TT + jn + tid];
            asm volatile("cp.async.commit_group;");
        }

        if (causal) {
            #pragma unroll
            for (int tn = 0; tn < 8; tn++) {
                int cb = tn*8 + cq*2;
                #pragma unroll
                for (int e = 0; e < 2; e++) {
                    int j = j0 + cb + e;
                    bool bad = (padsm[st][cb + e] == 0.0f);
                    if (j > i0     || bad) S[tn][e]     = NEG;
                    if (j > i0 + 8 || bad) S[tn][2 + e] = NEG;
                }
            }
        }

        float mr0 = NEG, mr1 = NEG;
        #pragma unroll
        for (int tn = 0; tn < 8; tn++) {
            mr0 = fmaxf(mr0, fmaxf(S[tn][0], S[tn][1]));
            mr1 = fmaxf(mr1, fmaxf(S[tn][2], S[tn][3]));
        }
        mr0 = fmaxf(mr0, __shfl_xor_sync(0xFFFFFFFFu, mr0, 1));
        mr0 = fmaxf(mr0, __shfl_xor_sync(0xFFFFFFFFu, mr0, 2));
        mr1 = fmaxf(mr1, __shfl_xor_sync(0xFFFFFFFFu, mr1, 1));
        mr1 = fmaxf(mr1, __shfl_xor_sync(0xFFFFFFFFu, mr1, 2));

        float mn0 = fmaxf(m0, mr0), mn1 = fmaxf(m1, mr1);
        float ms0 = (mn0 == NEG) ? 0.f : mn0;
        float ms1 = (mn1 == NEG) ? 0.f : mn1;
        float c0 = exp2f(m0 - ms0), c1 = exp2f(m1 - ms1);

        float P[8][4];
        float s0 = 0.f, s1 = 0.f;
        #pragma unroll
        for (int tn = 0; tn < 8; tn++) {
            P[tn][0] = exp2f(S[tn][0] - ms0);
            P[tn][1] = exp2f(S[tn][1] - ms0);
            P[tn][2] = exp2f(S[tn][2] - ms1);
            P[tn][3] = exp2f(S[tn][3] - ms1);
            s0 += P[tn][0] + P[tn][1];
            s1 += P[tn][2] + P[tn][3];
        }
        s0 += __shfl_xor_sync(0xFFFFFFFFu, s0, 1);
        s0 += __shfl_xor_sync(0xFFFFFFFFu, s0, 2);
        s1 += __shfl_xor_sync(0xFFFFFFFFu, s1, 1);
        s1 += __shfl_xor_sync(0xFFFFFFFFu, s1, 2);
        l0 = l0*c0 + s0;
        l1 = l1*c1 + s1;
        m0 = mn0; m1 = mn1;

        #pragma unroll
        for (int nt = 0; nt < 4; nt++) {
            Oa[nt][0] *= c0; Oa[nt][1] *= c0;
            Oa[nt][2] *= c1; Oa[nt][3] *= c1;
        }

        #pragma unroll
        for (int ks2 = 0; ks2 < 4; ks2++) {
            uint32_t vb[2][4];
            #pragma unroll
            for (int ng = 0; ng < 2; ng++) {
                uint32_t addr = svst + (uint32_t)((ks2*16 + (lane & 15))*80 + ng*32 + (lane >> 4)*16);
                asm volatile(
                    "ldmatrix.sync.aligned.m8n8.x4.trans.shared.b16 {%0,%1,%2,%3}, [%4];"
                    : "=r"(vb[ng][0]), "=r"(vb[ng][1]), "=r"(vb[ng][2]), "=r"(vb[ng][3])
                    : "r"(addr));
            }
            uint32_t pa0 = packh2(P[2*ks2][0],   P[2*ks2][1]);
            uint32_t pa1 = packh2(P[2*ks2][2],   P[2*ks2][3]);
            uint32_t pa2 = packh2(P[2*ks2+1][0], P[2*ks2+1][1]);
            uint32_t pa3 = packh2(P[2*ks2+1][2], P[2*ks2+1][3]);
            HMMA(Oa[0], pa0, pa1, pa2, pa3, vb[0][0], vb[0][1]);
            HMMA(Oa[1], pa0, pa1, pa2, pa3, vb[0][2], vb[0][3]);
            HMMA(Oa[2], pa0, pa1, pa2, pa3, vb[1][0], vb[1][1]);
            HMMA(Oa[3], pa0, pa1, pa2, pa3, vb[1][2], vb[1][3]);
        }

        if (t + 1 < t1) {
            asm volatile("cp.async.wait_group 0;");
            __syncthreads();
        }
    }

    if (cq == 0) {
        g_scratch[O_PM + pb0] = m0;  g_scratch[O_PL + pb0] = l0;
        g_scratch[O_PM + pb1] = m1;  g_scratch[O_PL + pb1] = l1;
    }
    #pragma unroll
    for (int nt = 0; nt < 4; nt++) {
        int c = nt*8 + cq*2;
        g_scratch[O_PO + pb0*32 + c]   = Oa[nt][0];
        g_scratch[O_PO + pb0*32 + c+1] = Oa[nt][1];
        g_scratch[O_PO + pb1*32 + c]   = Oa[nt][2];
        g_scratch[O_PO + pb1*32 + c+1] = Oa[nt][3];
    }
}

__global__ void k_fmerge(__half* __restrict__ O)
{
    int idx = blockIdx.x*256 + threadIdx.x;
    int qh = idx >> 5, d = idx & 31;
    float M = -CUDART_INF_F;
    #pragma unroll
    for (int s = 0; s < NSPLIT; s++)
        M = fmaxf(M, g_scratch[O_PM + (size_t)s*QH + qh]);
    float L = 0.0f, acc = 0.0f;
    #pragma unroll
    for (int s = 0; s < NSPLIT; s++) {
        size_t base = (size_t)s*QH + qh;
        float w = exp2f(g_scratch[O_PM + base] - M);
        L   += w * g_scratch[O_PL + base];
        acc += w * g_scratch[O_PO + base*32 + d];
    }
    int bh = qh / TT, i = qh % TT;
    int b = bh / HH, h = bh % HH;
    O[(size_t)(b*TT + i)*DD + h*32 + d] = __float2half(acc / L);
}

// ---------------- fused residual-add + LayerNorm -------------------------
__global__ void k_addln(const __half* __restrict__ X, const float* __restrict__ A,
                        const float* __restrict__ g, const float* __restrict__ be,
                        __half* __restrict__ Y)
{
    int r = blockIdx.x, d = threadIdx.x;
    float v = __half2float(X[(size_t)r*DD + d]) + A[(size_t)r*DD + d];
    __shared__ float sh[18];
    float s1 = v, s2 = v*v;
    #pragma unroll
    for (int off = 16; off; off >>= 1) {
        s1 += __shfl_down_sync(0xFFFFFFFFu, s1, off);
        s2 += __shfl_down_sync(0xFFFFFFFFu, s2, off);
    }
    int warp = d >> 5, lane = d & 31;
    if (lane == 0) { sh[warp] = s1; sh[8 + warp] = s2; }
    __syncthreads();
    if (d == 0) {
        float t1 = 0.f, t2 = 0.f;
        for (int w = 0; w < 8; w++) { t1 += sh[w]; t2 += sh[8 + w]; }
        float mean = t1 * (1.0f/256.0f);
        float var  = t2 * (1.0f/256.0f) - mean*mean;
        sh[16] = mean;
        sh[17] = rsqrtf(var + 1e-5f);
    }
    __syncthreads();
    Y[(size_t)r*DD + d] = __float2half((v - sh[16])*sh[17]*g[d] + be[d]);
}

// ---------------- host orchestration -------------------------------------
extern "C" void kernel_launch(void* const* d_in, const int* in_sizes, int n_in,
                              void* d_out, int out_size)
{
    const int*   src   = (const int*)  d_in[0];
    const int*   tgt   = (const int*)  d_in[1];
    const float* enc   = (const float*)d_in[2];
    const float* emb   = (const float*)d_in[3];
    const float* Wq_s  = (const float*)d_in[4];
    const float* Wk_s  = (const float*)d_in[5];
    const float* Wv_s  = (const float*)d_in[6];
    const float* Wo_s  = (const float*)d_in[7];
    const float* bo_s  = (const float*)d_in[8];
    const float* Wq_c  = (const float*)d_in[9];
    const float* Wk_c  = (const float*)d_in[10];
    const float* Wv_c  = (const float*)d_in[11];
    const float* Wo_c  = (const float*)d_in[12];
    const float* bo_c  = (const float*)d_in[13];
    const float* W1    = (const float*)d_in[14];
    const float* b1    = (const float*)d_in[15];
    const float* W2    = (const float*)d_in[16];
    const float* b2    = (const float*)d_in[17];
    const float* g1    = (const float*)d_in[18];
    const float* be1   = (const float*)d_in[19];
    const float* g2    = (const float*)d_in[20];
    const float* be2   = (const float*)d_in[21];
    const float* g3    = (const float*)d_in[22];
    const float* be3   = (const float*)d_in[23];
    const float* Wf    = (const float*)d_in[24];
    const float* bf    = (const float*)d_in[25];
    float* out = (float*)d_out;

    float* s = nullptr;
    cudaGetSymbolAddress((void**)&s, g_scratch);
    __half* x0h  = (__half*)(s + O_X0);
    __half* x1h  = (__half*)(s + O_X1);
    __half* x2h  = (__half*)(s + O_X2);
    __half* x3h  = (__half*)(s + O_X3);
    __half* qh_  = (__half*)(s + O_Q);
    __half* kh_  = (__half*)(s + O_K);
    __half* vh_  = (__half*)(s + O_V);
    __half* atth = (__half*)(s + O_ATT);
    float*  proj = s + O_PROJ;
    __half* ench = (__half*)(s + O_ENCZ);
    __half* ffh  = (__half*)(s + O_FF);
    __half* kch  = (__half*)(s + O_KC);
    __half* vch  = (__half*)(s + O_VC);
    __half* whA  = (__half*)(s + O_WH);
    __half* w1h  = (__half*)(s + O_W1H);
    __half* w2h  = (__half*)(s + O_W2H);
    __half* wfh  = (__half*)(s + O_WFH);

    __half* wqs = whA + 0*65536;
    __half* wks = whA + 1*65536;
    __half* wvs = whA + 2*65536;
    __half* wos = whA + 3*65536;
    __half* wqc = whA + 4*65536;
    __half* wkc = whA + 5*65536;
    __half* wvc = whA + 6*65536;
    __half* woc = whA + 7*65536;

    long long logitsN = (long long)BT * VOC;
    int write_ids = ((long long)out_size >= logitsN + BT);
    float* out_ids = out + logitsN;

    dim3 t32x8(32, 8);

    // ---- prep (ordered so launch #6 = the fused QKV GEMM for ncu) ----
    k_embedencz<<<BT + BB*SS, 256>>>(tgt, emb, x0h, src, enc, ench, out_ids, write_ids);
    k_transpW8<<<dim3(8, 8, 8), t32x8>>>(Wq_s, Wk_s, Wv_s, Wo_s, Wq_c, Wk_c, Wv_c, Wo_c, whA);
    k_transp<<<dim3(FFD/32, DD/32),  t32x8>>>(W1, w1h, DD, FFD);
    k_transp<<<dim3(DD/32,  FFD/32), t32x8>>>(W2, w2h, FFD, DD);
    k_transp<<<dim3(VOCP/32, DD/32), t32x8>>>(Wf, wfh, DD, VOC);

    // ---- self attention (+ cross K/V hoisted into the fused launch) ----
    k_hgemm5<<<dim3(2, 64, 5), 256>>>(x0h, ench, wqs, wks, wvs, wkc, wvc,
                                      qh_, kh_, vh_, kch, vch);
    k_fa2<<<dim3(BB*HH, TT/64, NSPLIT), 128>>>(qh_, kh_, vh_, TT, 1);
    k_fmerge<<<QH*32/256, 256>>>(atth);
    k_hgemm64<<<dim3(2, 64), 256>>>(atth, wos, bo_s, proj, DD, DD, 0);
    k_addln<<<BT, 256>>>(x0h, proj, g1, be1, x1h);

    // ---- cross attention ----
    k_hgemm64<<<dim3(2, 64), 256>>>(x1h, wqc, nullptr, qh_, DD, DD, 2);
    k_fa2<<<dim3(BB*HH, TT/64, NSPLIT), 128>>>(qh_, kch, vch, SS, 0);
    k_fmerge<<<QH*32/256, 256>>>(atth);
    k_hgemm64<<<dim3(2, 64), 256>>>(atth, woc, bo_c, proj, DD, DD, 0);
    k_addln<<<BT, 256>>>(x1h, proj, g2, be2, x2h);

    // ---- feed forward ----
    k_hgemm<<<dim3(16, 32), 256>>>(x2h, w1h, b1, ffh, BT, FFD, DD, 3);
    k_hgemm64<<<dim3(2, 64), 256>>>(ffh, w2h, b2, proj, DD, FFD, 0);
    k_addln<<<BT, 256>>>(x2h, proj, g3, be3, x3h);

    // ---- vocab projection into d_out ----
    k_hgemm<<<dim3(VOCP/128, 32), 256>>>(x3h, wfh, bf, out, BT, VOC, DD, 0);
}

// round 17
// speedup vs baseline: 2.6821x; 1.0342x over previous
#include <cuda_runtime.h>
#include <cuda_fp16.h>
#include <math.h>
#include <math_constants.h>
#include <stdint.h>

#define BB 2
#define TT 2048
#define SS 2048
#define DD 256
#define HH 8
#define FFD 2048
#define VOC 25426
#define VOCP 25472              // padded vocab (199*128)
#define BT (BB*TT)
#define QH (BB*HH*TT)           // 32768
#define NSELF 8
#define NCROSS 4

// ---------------- scratch ----------------
#define SLAB 1048576
#define O_X0   (0*SLAB)
#define O_X1   (1*SLAB)
#define O_X2   (2*SLAB)
#define O_X3   (3*SLAB)
#define O_Q    (4*SLAB)
#define O_K    (5*SLAB)
#define O_V    (6*SLAB)
#define O_ATT  (7*SLAB)
#define O_PROJ (8*SLAB)
#define O_ENCZ (9*SLAB)
#define O_FF   ((size_t)10*SLAB)                 // ff halves
#define O_KC   ((size_t)14*SLAB)
#define O_VC   ((size_t)15*SLAB)
#define O_PO   ((size_t)18*SLAB)                 // 8 splits x 1 slab
#define O_PM   ((size_t)26*SLAB)
#define O_PL   ((size_t)26*SLAB + 8*QH)
#define O_WH   ((size_t)27*SLAB)                 // 8 att weights fp16 [256][256]
#define O_W1H  (O_WH  + 8*32768)
#define O_W2H  (O_W1H + 262144)
#define O_WFH  (O_W2H + 262144)                  // [VOCP][256] fp16
#define SCRATCH_FLOATS ((size_t)35*SLAB)

__device__ float g_scratch[SCRATCH_FLOATS];
__device__ float g_padbuf[BT];

__device__ __forceinline__ float gelu_f(float v) {
    return 0.5f*v*(1.0f + erff(v*0.70710678118654752f));
}
__device__ __forceinline__ void cp16(uint32_t dst, const void* src) {
    asm volatile("cp.async.cg.shared.global [%0], [%1], 16;" :: "r"(dst), "l"(src));
}
#define HMMA(acc, a0, a1, a2, a3, b0, b1) \
    asm volatile( \
        "mma.sync.aligned.m16n8k16.row.col.f32.f16.f16.f32 " \
        "{%0,%1,%2,%3}, {%4,%5,%6,%7}, {%8,%9}, {%0,%1,%2,%3};" \
        : "+f"((acc)[0]), "+f"((acc)[1]), "+f"((acc)[2]), "+f"((acc)[3]) \
        : "r"(a0), "r"(a1), "r"(a2), "r"(a3), "r"(b0), "r"(b1))

__device__ __forceinline__ uint32_t packh2(float lo, float hi) {
    uint32_t u;
    asm("cvt.rn.f16x2.f32 %0, %1, %2;" : "=r"(u) : "f"(hi), "f"(lo));
    return u;
}

// ---------------- fused embedding/PE + encoder-zero ----------------
__global__ void k_embedencz(const int* __restrict__ tgt_in, const float* __restrict__ emb,
                            __half* __restrict__ X,
                            const int* __restrict__ src, const float* __restrict__ enc,
                            __half* __restrict__ E,
                            float* __restrict__ out_ids, int write_ids)
{
    int r = blockIdx.x;
    int d = threadIdx.x;
    if (r < BT) {
        int b = r / TT, t = r % TT;
        int id = (t == 0) ? VOC : tgt_in[b*(TT-1) + (t-1)];
        if (d == 0) {
            g_padbuf[r] = (id != 0) ? 1.0f : 0.0f;
            if (write_ids) out_ids[r] = (t == 0) ? 0.0f : (float)id;
        }
        int i2 = d & ~1;
        float div = __expf(-(float)i2 * (9.210340371976184f / 256.0f));
        float ang = (float)t * div;
        float pe  = (d & 1) ? cosf(ang) : sinf(ang);
        X[(size_t)r*DD + d] = __float2half(2.0f*emb[(size_t)id*DD + d] + pe);
    } else {
        int rr = r - BT;
        E[(size_t)rr*DD + d] = __float2half((src[rr] != 0) ? enc[(size_t)rr*DD + d] : 0.0f);
    }
}

// ---------------- ALL weight transposes in one kernel ----------------
// blocks: [0,512) att 8x(8x8); [512,1024) W1 (64x8); [1024,1536) W2 (8x64);
// [1536,7904) Wf (796x8). Each block = one 32x32 tile transpose fp32->fp16.
__global__ void __launch_bounds__(256)
k_transpall(const float* a0, const float* a1, const float* a2, const float* a3,
            const float* a4, const float* a5, const float* a6, const float* a7,
            const float* W1, const float* W2, const float* Wf)
{
    __shared__ float t[32][33];
    int blk = blockIdx.x;
    const float* src; __half* dst; int K, N, n0, k0;
    float sc = 1.0f;
    if (blk < 512) {
        int w = blk >> 6, rem = blk & 63;
        switch (w) {
            case 0: src = a0; break; case 1: src = a1; break;
            case 2: src = a2; break; case 3: src = a3; break;
            case 4: src = a4; break; case 5: src = a5; break;
            case 6: src = a6; break; default: src = a7; break;
        }
        dst = (__half*)(g_scratch + O_WH) + (size_t)w*65536;
        K = 256; N = 256;
        n0 = (rem & 7)*32; k0 = (rem >> 3)*32;
        if (w == 0 || w == 4) sc = 0.17677669529663687f * 1.4426950408889634f;
    } else if (blk < 1024) {
        int rem = blk - 512;
        src = W1; dst = (__half*)(g_scratch + O_W1H); K = 256; N = 2048;
        n0 = (rem & 63)*32; k0 = (rem >> 6)*32;
    } else if (blk < 1536) {
        int rem = blk - 1024;
        src = W2; dst = (__half*)(g_scratch + O_W2H); K = 2048; N = 256;
        n0 = (rem & 7)*32; k0 = (rem >> 3)*32;
    } else {
        int rem = blk - 1536;
        src = Wf; dst = (__half*)(g_scratch + O_WFH); K = 256; N = VOC;
        n0 = (rem % 796)*32; k0 = (rem / 796)*32;
    }
    int tx = threadIdx.x & 31, ty = threadIdx.x >> 5;
    #pragma unroll
    for (int j = 0; j < 4; j++) {
        int n = n0 + tx;
        t[ty + j*8][tx] = (n < N) ? src[(size_t)(k0 + ty + j*8)*N + n] : 0.0f;
    }
    __syncthreads();
    #pragma unroll
    for (int j = 0; j < 4; j++)
        dst[(size_t)(n0 + ty + j*8)*K + k0 + tx] = __float2half(t[tx][ty + j*8] * sc);
}

// ================= fp16 mma.sync GEMM, 128x128 tile, 3-stage ==============
#define HTILE 10240
#define HSTAGE (2*HTILE)
#define HSMEM (3*HSTAGE)

__device__ __forceinline__ void hgemm_core(
    const __half* __restrict__ A, const __half* __restrict__ Bm,
    const float* __restrict__ bias, void* Cv,
    int M, int N, int K, int flags, char* sm)
{
    uint32_t sb = (uint32_t)__cvta_generic_to_shared(sm);
    int tid = threadIdx.x;
    int lane = tid & 31, warp = tid >> 5;
    int wm0 = (warp >> 2) * 64, wn0 = (warp & 3) * 32;
    int m0 = blockIdx.y * 128, n0 = blockIdx.x * 128;

    int r0 = tid >> 2, c0 = tid & 3;
    int r1 = (tid + 256) >> 2, c1 = tid & 3;

    const __half* srcA = A + (size_t)m0*K;
    const __half* srcB = Bm + (size_t)n0*K;

    uint32_t aBase = sb + (uint32_t)((wm0 + (lane & 15))*80 + (lane >> 4)*16);
    uint32_t bBase = sb + 10240u + (uint32_t)((wn0 + (lane & 15))*80 + (lane >> 4)*16);

    float acc[4][4][4];
    #pragma unroll
    for (int i = 0; i < 4; i++)
        #pragma unroll
        for (int j = 0; j < 4; j++) {
            acc[i][j][0]=0.f; acc[i][j][1]=0.f; acc[i][j][2]=0.f; acc[i][j][3]=0.f;
        }

    int nk = K >> 5;          // >= 2 for all users (K=256)

    auto loadT = [&](int kt, int buf) {
        int k0 = kt << 5;
        uint32_t st = sb + (uint32_t)buf*HSTAGE;
        cp16(st + (uint32_t)(r0*80 + c0*16),          srcA + (size_t)r0*K + k0 + c0*8);
        cp16(st + (uint32_t)(r1*80 + c1*16),          srcA + (size_t)r1*K + k0 + c1*8);
        cp16(st + 10240u + (uint32_t)(r0*80 + c0*16), srcB + (size_t)r0*K + k0 + c0*8);
        cp16(st + 10240u + (uint32_t)(r1*80 + c1*16), srcB + (size_t)r1*K + k0 + c1*8);
        asm volatile("cp.async.commit_group;");
    };

    loadT(0, 0);
    loadT(1, 1);

    for (int kt = 0; kt < nk; kt++) {
        if (kt + 1 < nk) asm volatile("cp.async.wait_group 1;");
        else             asm volatile("cp.async.wait_group 0;");
        __syncthreads();
        if (kt + 2 < nk) loadT(kt + 2, (kt + 2) % 3);

        int buf = kt % 3;
        uint32_t aB = aBase + (uint32_t)buf*HSTAGE;
        uint32_t bB = bBase + (uint32_t)buf*HSTAGE;

        #pragma unroll
        for (int ks = 0; ks < 2; ks++) {
            uint32_t af[4][4], bf2[2][4];
            #pragma unroll
            for (int mt = 0; mt < 4; mt++) {
                uint32_t addr = aB + (uint32_t)(mt*16*80 + ks*32);
                asm volatile(
                    "ldmatrix.sync.aligned.m8n8.x4.shared.b16 {%0,%1,%2,%3}, [%4];"
                    : "=r"(af[mt][0]), "=r"(af[mt][1]), "=r"(af[mt][2]), "=r"(af[mt][3])
                    : "r"(addr));
            }
            #pragma unroll
            for (int nt16 = 0; nt16 < 2; nt16++) {
                uint32_t addr = bB + (uint32_t)(nt16*16*80 + ks*32);
                asm volatile(
                    "ldmatrix.sync.aligned.m8n8.x4.shared.b16 {%0,%1,%2,%3}, [%4];"
                    : "=r"(bf2[nt16][0]), "=r"(bf2[nt16][1]),
                      "=r"(bf2[nt16][2]), "=r"(bf2[nt16][3])
                    : "r"(addr));
            }
            #pragma unroll
            for (int mt = 0; mt < 4; mt++)
                #pragma unroll
                for (int nt = 0; nt < 4; nt++) {
                    uint32_t b0 = bf2[nt >> 1][nt & 1];
                    uint32_t b1 = bf2[nt >> 1][(nt & 1) + 2];
                    HMMA(acc[mt][nt], af[mt][0], af[mt][1], af[mt][2], af[mt][3], b0, b1);
                }
        }
    }

    int doGelu = flags & 1, outHalf = flags & 2;
    #pragma unroll
    for (int mt = 0; mt < 4; mt++) {
        int row0 = m0 + wm0 + mt*16 + (lane >> 2);
        #pragma unroll
        for (int nt = 0; nt < 4; nt++) {
            int col = n0 + wn0 + nt*8 + 2*(lane & 3);
            #pragma unroll
            for (int h = 0; h < 2; h++) {
                int rw = row0 + h*8;
                float v0 = acc[mt][nt][h*2+0];
                float v1 = acc[mt][nt][h*2+1];
                if (col + 1 < N) {
                    if (bias)  { v0 += bias[col]; v1 += bias[col+1]; }
                    if (doGelu){ v0 = gelu_f(v0); v1 = gelu_f(v1); }
                    if (outHalf) {
                        __half2 o; o.x = __float2half(v0); o.y = __float2half(v1);
                        *(__half2*)&((__half*)Cv)[(size_t)rw*N + col] = o;
                    } else {
                        float2 o; o.x = v0; o.y = v1;
                        *(float2*)&((float*)Cv)[(size_t)rw*N + col] = o;
                    }
                } else if (col < N) {
                    if (bias)  v0 += bias[col];
                    if (doGelu) v0 = gelu_f(v0);
                    if (outHalf) ((__half*)Cv)[(size_t)rw*N + col] = __float2half(v0);
                    else         ((float*)Cv)[(size_t)rw*N + col] = v0;
                }
            }
        }
    }
}

__global__ void __launch_bounds__(256)
k_hgemm(const __half* __restrict__ A, const __half* __restrict__ Bm,
        const float* __restrict__ bias, void* Cv, int M, int N, int K, int flags)
{
    extern __shared__ __align__(128) char smdyn[];
    hgemm_core(A, Bm, bias, Cv, M, N, K, flags, smdyn);
}

// ================= fp16 mma.sync GEMM, 64x128 tile, 2-stage ===============
#define H64A 5120
#define H64STAGE 15360

__device__ __forceinline__ void hgemm64_core(
    const __half* __restrict__ A, const __half* __restrict__ Bm,
    const float* __restrict__ bias, void* Cv,
    int N, int ldk, int kStart, int kLen, int flags, char* sm)
{
    uint32_t sb = (uint32_t)__cvta_generic_to_shared(sm);
    int tid = threadIdx.x;
    int lane = tid & 31, warp = tid >> 5;
    int wm0 = (warp >> 2) * 32, wn0 = (warp & 3) * 32;
    int m0 = blockIdx.y * 64, n0 = blockIdx.x * 128;

    int ra = tid >> 2, ca = tid & 3;
    int rb0 = tid >> 2, rb1 = (tid + 256) >> 2;

    const __half* srcA = A + (size_t)m0*ldk + kStart;
    const __half* srcB = Bm + (size_t)n0*ldk + kStart;

    uint32_t aBase = sb + (uint32_t)((wm0 + (lane & 15))*80 + (lane >> 4)*16);
    uint32_t bBase = sb + (uint32_t)H64A + (uint32_t)((wn0 + (lane & 15))*80 + (lane >> 4)*16);

    float acc[2][4][4];
    #pragma unroll
    for (int i = 0; i < 2; i++)
        #pragma unroll
        for (int j = 0; j < 4; j++) {
            acc[i][j][0]=0.f; acc[i][j][1]=0.f; acc[i][j][2]=0.f; acc[i][j][3]=0.f;
        }

    int nk = kLen >> 5;
    {
        uint32_t st = sb;
        cp16(st + (uint32_t)(ra*80 + ca*16),          srcA + (size_t)ra*ldk + ca*8);
        cp16(st + H64A + (uint32_t)(rb0*80 + ca*16),  srcB + (size_t)rb0*ldk + ca*8);
        cp16(st + H64A + (uint32_t)(rb1*80 + ca*16),  srcB + (size_t)rb1*ldk + ca*8);
        asm volatile("cp.async.commit_group;");
        asm volatile("cp.async.wait_group 0;");
    }
    __syncthreads();

    for (int kt = 0; kt < nk; kt++) {
        int cur = kt & 1;
        if (kt + 1 < nk) {
            int k0 = (kt + 1) << 5;
            uint32_t st = sb + (uint32_t)(cur ^ 1)*H64STAGE;
            cp16(st + (uint32_t)(ra*80 + ca*16),          srcA + (size_t)ra*ldk + k0 + ca*8);
            cp16(st + H64A + (uint32_t)(rb0*80 + ca*16),  srcB + (size_t)rb0*ldk + k0 + ca*8);
            cp16(st + H64A + (uint32_t)(rb1*80 + ca*16),  srcB + (size_t)rb1*ldk + k0 + ca*8);
            asm volatile("cp.async.commit_group;");
        }

        uint32_t aB = aBase + (uint32_t)cur*H64STAGE;
        uint32_t bB = bBase + (uint32_t)cur*H64STAGE;

        #pragma unroll
        for (int ks = 0; ks < 2; ks++) {
            uint32_t af[2][4], bf2[2][4];
            #pragma unroll
            for (int mt = 0; mt < 2; mt++) {
                uint32_t addr = aB + (uint32_t)(mt*16*80 + ks*32);
                asm volatile(
                    "ldmatrix.sync.aligned.m8n8.x4.shared.b16 {%0,%1,%2,%3}, [%4];"
                    : "=r"(af[mt][0]), "=r"(af[mt][1]), "=r"(af[mt][2]), "=r"(af[mt][3])
                    : "r"(addr));
            }
            #pragma unroll
            for (int nt16 = 0; nt16 < 2; nt16++) {
                uint32_t addr = bB + (uint32_t)(nt16*16*80 + ks*32);
                asm volatile(
                    "ldmatrix.sync.aligned.m8n8.x4.shared.b16 {%0,%1,%2,%3}, [%4];"
                    : "=r"(bf2[nt16][0]), "=r"(bf2[nt16][1]),
                      "=r"(bf2[nt16][2]), "=r"(bf2[nt16][3])
                    : "r"(addr));
            }
            #pragma unroll
            for (int mt = 0; mt < 2; mt++)
                #pragma unroll
                for (int nt = 0; nt < 4; nt++) {
                    uint32_t b0 = bf2[nt >> 1][nt & 1];
                    uint32_t b1 = bf2[nt >> 1][(nt & 1) + 2];
                    HMMA(acc[mt][nt], af[mt][0], af[mt][1], af[mt][2], af[mt][3], b0, b1);
                }
        }

        if (kt + 1 < nk) {
            asm volatile("cp.async.wait_group 0;");
            __syncthreads();
        }
    }

    int doGelu = flags & 1, outHalf = flags & 2;
    #pragma unroll
    for (int mt = 0; mt < 2; mt++) {
        int row0 = m0 + wm0 + mt*16 + (lane >> 2);
        #pragma unroll
        for (int nt = 0; nt < 4; nt++) {
            int col = n0 + wn0 + nt*8 + 2*(lane & 3);
            #pragma unroll
            for (int h = 0; h < 2; h++) {
                int rw = row0 + h*8;
                float v0 = acc[mt][nt][h*2+0];
                float v1 = acc[mt][nt][h*2+1];
                if (col + 1 < N) {
                    if (bias)  { v0 += bias[col]; v1 += bias[col+1]; }
                    if (doGelu){ v0 = gelu_f(v0); v1 = gelu_f(v1); }
                    if (outHalf) {
                        __half2 o; o.x = __float2half(v0); o.y = __float2half(v1);
                        *(__half2*)&((__half*)Cv)[(size_t)rw*N + col] = o;
                    } else {
                        float2 o; o.x = v0; o.y = v1;
                        *(float2*)&((float*)Cv)[(size_t)rw*N + col] = o;
                    }
                }
            }
        }
    }
}

__global__ void __launch_bounds__(256)
k_hgemm64(const __half* __restrict__ A, const __half* __restrict__ Bm,
          const float* __restrict__ bias, void* Cv, int N, int K, int flags)
{
    __shared__ __align__(128) char sm[2*H64STAGE];
    hgemm64_core(A, Bm, bias, Cv, N, K, 0, K, flags, sm);
}

// fused 5-way: self Q,K,V + cross K,V. grid (2, 64, 5).
__global__ void __launch_bounds__(256)
k_hgemm5(const __half* xs, const __half* ec,
         const __half* w0, const __half* w1, const __half* w2,
         const __half* w3, const __half* w4,
         __half* c0, __half* c1, __half* c2, __half* c3, __half* c4)
{
    __shared__ __align__(128) char sm[2*H64STAGE];
    const __half* A; const __half* W; __half* C;
    switch (blockIdx.z) {
        case 0: A = xs; W = w0; C = c0; break;
        case 1: A = xs; W = w1; C = c1; break;
        case 2: A = xs; W = w2; C = c2; break;
        case 3: A = ec; W = w3; C = c3; break;
        default:A = ec; W = w4; C = c4; break;
    }
    hgemm64_core(A, W, nullptr, C, DD, DD, 0, DD, 2, sm);
}

// FFN2 split-K x2: z selects K half; partials into O_Q / O_K slabs (fp32).
__global__ void __launch_bounds__(256)
k_ffn2(const __half* __restrict__ ff, const __half* __restrict__ w2)
{
    __shared__ __align__(128) char sm[2*H64STAGE];
    float* C = g_scratch + (blockIdx.z ? O_K : O_Q);
    hgemm64_core(ff, w2, nullptr, C, DD, FFD, blockIdx.z*(FFD/2), FFD/2, 0, sm);
}

// ================= FA2 flash attention, interleaved KV-splits =============
__global__ void __launch_bounds__(128)
k_fa2(const __half* __restrict__ Q, const __half* __restrict__ Kp,
      const __half* __restrict__ Vp, int lenK, int causal)
{
    __shared__ __align__(128) __half Qs[64*40];
    __shared__ __align__(128) __half KsS[2][64*40];
    __shared__ __align__(128) __half VsS[2][64*40];
    __shared__ float padsm[2][64];

    uint32_t sq  = (uint32_t)__cvta_generic_to_shared(Qs);
    uint32_t sk0 = (uint32_t)__cvta_generic_to_shared(KsS);
    uint32_t sv0 = (uint32_t)__cvta_generic_to_shared(VsS);

    int tid = threadIdx.x, lane = tid & 31, warp = tid >> 5;
    int bh = blockIdx.x, b = bh >> 3, h = bh & 7;
    int yb = blockIdx.y, z = blockIdx.z;
    int nsplit = gridDim.z;
    int qbase = yb*64;

    int limit = lenK >> 6;
    if (causal) { int need = yb + 1; if (limit > need) limit = need; }

    int r = lane >> 2, cq = lane & 3;
    int i0 = qbase + warp*16 + r;
    size_t pb0 = (size_t)z*QH + (size_t)bh*TT + i0;
    size_t pb1 = pb0 + 8;

    if (z >= limit) {                              // empty split
        if (cq == 0) {
            g_scratch[O_PM + pb0] = -CUDART_INF_F;  g_scratch[O_PL + pb0] = 0.f;
            g_scratch[O_PM + pb1] = -CUDART_INF_F;  g_scratch[O_PL + pb1] = 0.f;
        }
        #pragma unroll
        for (int nt = 0; nt < 4; nt++) {
            int c = nt*8 + cq*2;
            g_scratch[O_PO + pb0*32 + c]   = 0.f;
            g_scratch[O_PO + pb0*32 + c+1] = 0.f;
            g_scratch[O_PO + pb1*32 + c]   = 0.f;
            g_scratch[O_PO + pb1*32 + c+1] = 0.f;
        }
        return;
    }

    #pragma unroll
    for (int ii = 0; ii < 2; ii++) {
        int idx = tid + ii*128;
        int rr = idx >> 2, cc = idx & 3;
        cp16(sq + (uint32_t)(rr*80 + cc*16),
             Q + ((size_t)(b*TT + qbase + rr))*DD + h*32 + cc*8);
    }
    {
        int j0 = z*64;
        const __half* kb_ = Kp + ((size_t)b*lenK + j0)*DD + h*32;
        const __half* vb_ = Vp + ((size_t)b*lenK + j0)*DD + h*32;
        #pragma unroll
        for (int ii = 0; ii < 2; ii++) {
            int idx = tid + ii*128;
            int rr = idx >> 2, cc = idx & 3;
            cp16(sk0 + (uint32_t)(rr*80 + cc*16), kb_ + (size_t)rr*DD + cc*8);
            cp16(sv0 + (uint32_t)(rr*80 + cc*16), vb_ + (size_t)rr*DD + cc*8);
        }
        if (causal && tid < 64) padsm[0][tid] = g_padbuf[b*TT + j0 + tid];
    }
    asm volatile("cp.async.commit_group;");
    asm volatile("cp.async.wait_group 0;");
    __syncthreads();

    uint32_t aq[2][4];
    #pragma unroll
    for (int ks = 0; ks < 2; ks++) {
        uint32_t addr = sq + (uint32_t)((warp*16 + (lane & 15))*80 + ks*32 + (lane >> 4)*16);
        asm volatile(
            "ldmatrix.sync.aligned.m8n8.x4.shared.b16 {%0,%1,%2,%3}, [%4];"
            : "=r"(aq[ks][0]), "=r"(aq[ks][1]), "=r"(aq[ks][2]), "=r"(aq[ks][3])
            : "r"(addr));
    }

    const float NEG = -CUDART_INF_F;
    float m0 = NEG, m1 = NEG, l0 = 0.f, l1 = 0.f;
    float Oa[4][4];
    #pragma unroll
    for (int i = 0; i < 4; i++) { Oa[i][0]=0.f; Oa[i][1]=0.f; Oa[i][2]=0.f; Oa[i][3]=0.f; }

    int it = 0;
    for (int t = z; t < limit; t += nsplit, it++) {
        int st = it & 1;
        int j0 = t*64;
        uint32_t skst = sk0 + (uint32_t)st*5120u;
        uint32_t svst = sv0 + (uint32_t)st*5120u;

        float S[8][4];
        #pragma unroll
        for (int i = 0; i < 8; i++) { S[i][0]=0.f; S[i][1]=0.f; S[i][2]=0.f; S[i][3]=0.f; }
        #pragma unroll
        for (int ks = 0; ks < 2; ks++) {
            uint32_t kb[4][4];
            #pragma unroll
            for (int g = 0; g < 4; g++) {
                uint32_t addr = skst + (uint32_t)((g*16 + (lane & 15))*80 + ks*32 + (lane >> 4)*16);
                asm volatile(
                    "ldmatrix.sync.aligned.m8n8.x4.shared.b16 {%0,%1,%2,%3}, [%4];"
                    : "=r"(kb[g][0]), "=r"(kb[g][1]), "=r"(kb[g][2]), "=r"(kb[g][3])
                    : "r"(addr));
            }
            #pragma unroll
            for (int g = 0; g < 4; g++) {
                HMMA(S[2*g],   aq[ks][0], aq[ks][1], aq[ks][2], aq[ks][3], kb[g][0], kb[g][2]);
                HMMA(S[2*g+1], aq[ks][0], aq[ks][1], aq[ks][2], aq[ks][3], kb[g][1], kb[g][3]);
            }
        }

        int tn = t + nsplit;
        if (tn < limit) {
            int jn = tn*64;
            uint32_t skn = sk0 + (uint32_t)(st ^ 1)*5120u;
            uint32_t svn = sv0 + (uint32_t)(st ^ 1)*5120u;
            const __half* kb_ = Kp + ((size_t)b*lenK + jn)*DD + h*32;
            const __half* vb_ = Vp + ((size_t)b*lenK + jn)*DD + h*32;
            #pragma unroll
            for (int ii = 0; ii < 2; ii++) {
                int idx = tid + ii*128;
                int rr = idx >> 2, cc = idx & 3;
                cp16(skn + (uint32_t)(rr*80 + cc*16), kb_ + (size_t)rr*DD + cc*8);
                cp16(svn + (uint32_t)(rr*80 + cc*16), vb_ + (size_t)rr*DD + cc*8);
            }
            if (causal && tid < 64) padsm[st ^ 1][tid] = g_padbuf[b*TT + jn + tid];
            asm volatile("cp.async.commit_group;");
        }

        if (causal) {
            #pragma unroll
            for (int tnn = 0; tnn < 8; tnn++) {
                int cb = tnn*8 + cq*2;
                #pragma unroll
                for (int e = 0; e < 2; e++) {
                    int j = j0 + cb + e;
                    bool bad = (padsm[st][cb + e] == 0.0f);
                    if (j > i0     || bad) S[tnn][e]     = NEG;
                    if (j > i0 + 8 || bad) S[tnn][2 + e] = NEG;
                }
            }
        }

        float mr0 = NEG, mr1 = NEG;
        #pragma unroll
        for (int tnn = 0; tnn < 8; tnn++) {
            mr0 = fmaxf(mr0, fmaxf(S[tnn][0], S[tnn][1]));
            mr1 = fmaxf(mr1, fmaxf(S[tnn][2], S[tnn][3]));
        }
        mr0 = fmaxf(mr0, __shfl_xor_sync(0xFFFFFFFFu, mr0, 1));
        mr0 = fmaxf(mr0, __shfl_xor_sync(0xFFFFFFFFu, mr0, 2));
        mr1 = fmaxf(mr1, __shfl_xor_sync(0xFFFFFFFFu, mr1, 1));
        mr1 = fmaxf(mr1, __shfl_xor_sync(0xFFFFFFFFu, mr1, 2));

        float mn0 = fmaxf(m0, mr0), mn1 = fmaxf(m1, mr1);
        float ms0 = (mn0 == NEG) ? 0.f : mn0;
        float ms1 = (mn1 == NEG) ? 0.f : mn1;
        float c0 = exp2f(m0 - ms0), c1 = exp2f(m1 - ms1);

        float P[8][4];
        float s0 = 0.f, s1 = 0.f;
        #pragma unroll
        for (int tnn = 0; tnn < 8; tnn++) {
            P[tnn][0] = exp2f(S[tnn][0] - ms0);
            P[tnn][1] = exp2f(S[tnn][1] - ms0);
            P[tnn][2] = exp2f(S[tnn][2] - ms1);
            P[tnn][3] = exp2f(S[tnn][3] - ms1);
            s0 += P[tnn][0] + P[tnn][1];
            s1 += P[tnn][2] + P[tnn][3];
        }
        s0 += __shfl_xor_sync(0xFFFFFFFFu, s0, 1);
        s0 += __shfl_xor_sync(0xFFFFFFFFu, s0, 2);
        s1 += __shfl_xor_sync(0xFFFFFFFFu, s1, 1);
        s1 += __shfl_xor_sync(0xFFFFFFFFu, s1, 2);
        l0 = l0*c0 + s0;
        l1 = l1*c1 + s1;
        m0 = mn0; m1 = mn1;

        #pragma unroll
        for (int nt = 0; nt < 4; nt++) {
            Oa[nt][0] *= c0; Oa[nt][1] *= c0;
            Oa[nt][2] *= c1; Oa[nt][3] *= c1;
        }

        #pragma unroll
        for (int ks2 = 0; ks2 < 4; ks2++) {
            uint32_t vb[2][4];
            #pragma unroll
            for (int ng = 0; ng < 2; ng++) {
                uint32_t addr = svst + (uint32_t)((ks2*16 + (lane & 15))*80 + ng*32 + (lane >> 4)*16);
                asm volatile(
                    "ldmatrix.sync.aligned.m8n8.x4.trans.shared.b16 {%0,%1,%2,%3}, [%4];"
                    : "=r"(vb[ng][0]), "=r"(vb[ng][1]), "=r"(vb[ng][2]), "=r"(vb[ng][3])
                    : "r"(addr));
            }
            uint32_t pa0 = packh2(P[2*ks2][0],   P[2*ks2][1]);
            uint32_t pa1 = packh2(P[2*ks2][2],   P[2*ks2][3]);
            uint32_t pa2 = packh2(P[2*ks2+1][0], P[2*ks2+1][1]);
            uint32_t pa3 = packh2(P[2*ks2+1][2], P[2*ks2+1][3]);
            HMMA(Oa[0], pa0, pa1, pa2, pa3, vb[0][0], vb[0][1]);
            HMMA(Oa[1], pa0, pa1, pa2, pa3, vb[0][2], vb[0][3]);
            HMMA(Oa[2], pa0, pa1, pa2, pa3, vb[1][0], vb[1][1]);
            HMMA(Oa[3], pa0, pa1, pa2, pa3, vb[1][2], vb[1][3]);
        }

        if (tn < limit) {
            asm volatile("cp.async.wait_group 0;");
            __syncthreads();
        }
    }

    if (cq == 0) {
        g_scratch[O_PM + pb0] = m0;  g_scratch[O_PL + pb0] = l0;
        g_scratch[O_PM + pb1] = m1;  g_scratch[O_PL + pb1] = l1;
    }
    #pragma unroll
    for (int nt = 0; nt < 4; nt++) {
        int c = nt*8 + cq*2;
        g_scratch[O_PO + pb0*32 + c]   = Oa[nt][0];
        g_scratch[O_PO + pb0*32 + c+1] = Oa[nt][1];
        g_scratch[O_PO + pb1*32 + c]   = Oa[nt][2];
        g_scratch[O_PO + pb1*32 + c+1] = Oa[nt][3];
    }
}

__global__ void k_fmerge(__half* __restrict__ O, int nsplit)
{
    int idx = blockIdx.x*256 + threadIdx.x;
    int qh = idx >> 5, d = idx & 31;
    float M = -CUDART_INF_F;
    for (int s = 0; s < nsplit; s++)
        M = fmaxf(M, g_scratch[O_PM + (size_t)s*QH + qh]);
    float L = 0.0f, acc = 0.0f;
    for (int s = 0; s < nsplit; s++) {
        size_t base = (size_t)s*QH + qh;
        float w = exp2f(g_scratch[O_PM + base] - M);
        L   += w * g_scratch[O_PL + base];
        acc += w * g_scratch[O_PO + base*32 + d];
    }
    int bh = qh / TT, i = qh % TT;
    int b = bh / HH, h = bh % HH;
    O[(size_t)(b*TT + i)*DD + h*32 + d] = __float2half(acc / L);
}

// ---------------- fused residual-add + LayerNorm -------------------------
__device__ __forceinline__ void addln_body(float v, int r, int d,
        const float* g, const float* be, __half* Y)
{
    __shared__ float sh[18];
    float s1 = v, s2 = v*v;
    #pragma unroll
    for (int off = 16; off; off >>= 1) {
        s1 += __shfl_down_sync(0xFFFFFFFFu, s1, off);
        s2 += __shfl_down_sync(0xFFFFFFFFu, s2, off);
    }
    int warp = d >> 5, lane = d & 31;
    if (lane == 0) { sh[warp] = s1; sh[8 + warp] = s2; }
    __syncthreads();
    if (d == 0) {
        float t1 = 0.f, t2 = 0.f;
        for (int w = 0; w < 8; w++) { t1 += sh[w]; t2 += sh[8 + w]; }
        float mean = t1 * (1.0f/256.0f);
        float var  = t2 * (1.0f/256.0f) - mean*mean;
        sh[16] = mean;
        sh[17] = rsqrtf(var + 1e-5f);
    }
    __syncthreads();
    Y[(size_t)r*DD + d] = __float2half((v - sh[16])*sh[17]*g[d] + be[d]);
}

__global__ void k_addln(const __half* __restrict__ X, const float* __restrict__ A,
                        const float* __restrict__ g, const float* __restrict__ be,
                        __half* __restrict__ Y)
{
    int r = blockIdx.x, d = threadIdx.x;
    float v = __half2float(X[(size_t)r*DD + d]) + A[(size_t)r*DD + d];
    addln_body(v, r, d, g, be, Y);
}

// x + b + (split-K partials in O_Q + O_K), then LN
__global__ void k_addln2(const __half* __restrict__ X, const float* __restrict__ bias,
                         const float* __restrict__ g, const float* __restrict__ be,
                         __half* __restrict__ Y)
{
    int r = blockIdx.x, d = threadIdx.x;
    size_t off = (size_t)r*DD + d;
    float v = __half2float(X[off]) + bias[d]
            + g_scratch[O_Q + off] + g_scratch[O_K + off];
    addln_body(v, r, d, g, be, Y);
}

// ---------------- host orchestration -------------------------------------
extern "C" void kernel_launch(void* const* d_in, const int* in_sizes, int n_in,
                              void* d_out, int out_size)
{
    const int*   src   = (const int*)  d_in[0];
    const int*   tgt   = (const int*)  d_in[1];
    const float* enc   = (const float*)d_in[2];
    const float* emb   = (const float*)d_in[3];
    const float* Wq_s  = (const float*)d_in[4];
    const float* Wk_s  = (const float*)d_in[5];
    const float* Wv_s  = (const float*)d_in[6];
    const float* Wo_s  = (const float*)d_in[7];
    const float* bo_s  = (const float*)d_in[8];
    const float* Wq_c  = (const float*)d_in[9];
    const float* Wk_c  = (const float*)d_in[10];
    const float* Wv_c  = (const float*)d_in[11];
    const float* Wo_c  = (const float*)d_in[12];
    const float* bo_c  = (const float*)d_in[13];
    const float* W1    = (const float*)d_in[14];
    const float* b1    = (const float*)d_in[15];
    const float* W2    = (const float*)d_in[16];
    const float* b2    = (const float*)d_in[17];
    const float* g1    = (const float*)d_in[18];
    const float* be1   = (const float*)d_in[19];
    const float* g2    = (const float*)d_in[20];
    const float* be2   = (const float*)d_in[21];
    const float* g3    = (const float*)d_in[22];
    const float* be3   = (const float*)d_in[23];
    const float* Wf    = (const float*)d_in[24];
    const float* bf    = (const float*)d_in[25];
    float* out = (float*)d_out;

    float* s = nullptr;
    cudaGetSymbolAddress((void**)&s, g_scratch);
    __half* x0h  = (__half*)(s + O_X0);
    __half* x1h  = (__half*)(s + O_X1);
    __half* x2h  = (__half*)(s + O_X2);
    __half* x3h  = (__half*)(s + O_X3);
    __half* qh_  = (__half*)(s + O_Q);
    __half* kh_  = (__half*)(s + O_K);
    __half* vh_  = (__half*)(s + O_V);
    __half* atth = (__half*)(s + O_ATT);
    float*  proj = s + O_PROJ;
    __half* ench = (__half*)(s + O_ENCZ);
    __half* ffh  = (__half*)(s + O_FF);
    __half* kch  = (__half*)(s + O_KC);
    __half* vch  = (__half*)(s + O_VC);
    __half* whA  = (__half*)(s + O_WH);
    __half* w1h  = (__half*)(s + O_W1H);
    __half* w2h  = (__half*)(s + O_W2H);
    __half* wfh  = (__half*)(s + O_WFH);

    __half* wqs = whA + 0*65536;
    __half* wks = whA + 1*65536;
    __half* wvs = whA + 2*65536;
    __half* wos = whA + 3*65536;
    __half* wqc = whA + 4*65536;
    __half* wkc = whA + 5*65536;
    __half* wvc = whA + 6*65536;
    __half* woc = whA + 7*65536;

    long long logitsN = (long long)BT * VOC;
    int write_ids = ((long long)out_size >= logitsN + BT);
    float* out_ids = out + logitsN;

    cudaFuncSetAttribute(k_hgemm, cudaFuncAttributeMaxDynamicSharedMemorySize, HSMEM);

    // ---- prep ----
    k_embedencz<<<BT + BB*SS, 256>>>(tgt, emb, x0h, src, enc, ench, out_ids, write_ids);
    k_transpall<<<7904, 256>>>(Wq_s, Wk_s, Wv_s, Wo_s, Wq_c, Wk_c, Wv_c, Wo_c, W1, W2, Wf);

    // ---- self attention (+ cross K/V hoisted) ----
    k_hgemm5<<<dim3(2, 64, 5), 256>>>(x0h, ench, wqs, wks, wvs, wkc, wvc,
                                      qh_, kh_, vh_, kch, vch);
    k_fa2<<<dim3(BB*HH, TT/64, NSELF), 128>>>(qh_, kh_, vh_, TT, 1);
    k_fmerge<<<QH*32/256, 256>>>(atth, NSELF);
    k_hgemm64<<<dim3(2, 64), 256>>>(atth, wos, bo_s, proj, DD, DD, 0);
    k_addln<<<BT, 256>>>(x0h, proj, g1, be1, x1h);

    // ---- cross attention ----
    k_hgemm64<<<dim3(2, 64), 256>>>(x1h, wqc, nullptr, qh_, DD, DD, 2);
    k_fa2<<<dim3(BB*HH, TT/64, NCROSS), 128>>>(qh_, kch, vch, SS, 0);
    k_fmerge<<<QH*32/256, 256>>>(atth, NCROSS);
    k_hgemm64<<<dim3(2, 64), 256>>>(atth, woc, bo_c, proj, DD, DD, 0);
    k_addln<<<BT, 256>>>(x1h, proj, g2, be2, x2h);

    // ---- feed forward ----
    k_hgemm<<<dim3(16, 32), 256, HSMEM>>>(x2h, w1h, b1, ffh, BT, FFD, DD, 3);
    k_ffn2<<<dim3(2, 64, 2), 256>>>(ffh, w2h);
    k_addln2<<<BT, 256>>>(x2h, b2, g3, be3, x3h);

    // ---- vocab projection into d_out ----
    k_hgemm<<<dim3(VOCP/128, 32), 256, HSMEM>>>(x3h, wfh, bf, out, BT, VOC, DD, 0);
}